// round 1
// baseline (speedup 1.0000x reference)
#include <cuda_runtime.h>

#define EPSF 1e-6f

// Problem constants (B=4, T=4096, D=1024, H=4, d=64)
#define BB    4
#define TT    4096
#define DDIM  1024
#define HH    4
#define HD    64
#define NTOK  (BB*TT)        // 16384
#define QKVW  768
#define CHUNK 64
#define NCH   (TT/CHUNK)     // 64
#define NBH   (BB*HH)        // 16
#define YSZ   (16777216)     // NTOK*DDIM
#define KVSZ  (65536)        // NBH*64*64

// ---------------- scratch (device globals; no allocations allowed) ----------
__device__ __align__(128) float g_qkv[(size_t)NTOK * QKVW];        // 48 MB
__device__ __align__(128) float g_y  [(size_t)NTOK * 256];         // 16 MB
__device__ __align__(128) float g_Sc [(size_t)NBH * NCH * 4096];   // 16 MB
__device__ __align__(128) float g_S0 [(size_t)NBH * NCH * 4096];   // 16 MB
__device__ __align__(128) float g_kc [(size_t)NBH * NCH * 64];
__device__ __align__(128) float g_kc0[(size_t)NBH * NCH * 64];

// ---------------- generic tiled SGEMM: C[m][n] = sum_k A[m][k]*B[n][k] ------
// 64x64 tile, BK=16, 256 threads, 4x4 per-thread microtile, float4 LDS.
__global__ void __launch_bounds__(256) sgemm_tn(
    const float* __restrict__ A, int lda,
    const float* __restrict__ B, int ldb,
    float* __restrict__ C, int ldc, int K)
{
    __shared__ float As[16][68];
    __shared__ float Bs[16][68];
    const int tid = threadIdx.x;
    const int tx = tid & 15, ty = tid >> 4;
    const int m0 = blockIdx.x * 64, n0 = blockIdx.y * 64;
    const int lr = tid >> 2;            // 0..63
    const int lk = (tid & 3) * 4;       // 0,4,8,12
    const float* Ag = A + (size_t)(m0 + lr) * lda + lk;
    const float* Bg = B + (size_t)(n0 + lr) * ldb + lk;

    float acc[4][4];
#pragma unroll
    for (int i = 0; i < 4; i++)
#pragma unroll
        for (int j = 0; j < 4; j++) acc[i][j] = 0.f;

    for (int k0 = 0; k0 < K; k0 += 16) {
        float4 a4 = *(const float4*)(Ag + k0);
        float4 b4 = *(const float4*)(Bg + k0);
        __syncthreads();
        As[lk + 0][lr] = a4.x; As[lk + 1][lr] = a4.y;
        As[lk + 2][lr] = a4.z; As[lk + 3][lr] = a4.w;
        Bs[lk + 0][lr] = b4.x; Bs[lk + 1][lr] = b4.y;
        Bs[lk + 2][lr] = b4.z; Bs[lk + 3][lr] = b4.w;
        __syncthreads();
#pragma unroll
        for (int kk = 0; kk < 16; kk++) {
            float4 av = *(const float4*)&As[kk][ty * 4];
            float4 bv = *(const float4*)&Bs[kk][tx * 4];
            float am[4] = {av.x, av.y, av.z, av.w};
            float bm[4] = {bv.x, bv.y, bv.z, bv.w};
#pragma unroll
            for (int i = 0; i < 4; i++)
#pragma unroll
                for (int j = 0; j < 4; j++)
                    acc[i][j] += am[i] * bm[j];
        }
    }
#pragma unroll
    for (int i = 0; i < 4; i++) {
        float4 o = make_float4(acc[i][0], acc[i][1], acc[i][2], acc[i][3]);
        *(float4*)(C + (size_t)(m0 + ty * 4 + i) * ldc + n0 + tx * 4) = o;
    }
}

// ---------------- pos_unit: p = elu(x)+1; p /= (||p||_2 per head + eps) ----
// one block per token; pass 0 = q cols [0,256), pass 1 = k cols [256,512)
__global__ void __launch_bounds__(256) posunit_kernel(float* __restrict__ qkv)
{
    __shared__ float wsum[8];
    const int n = blockIdx.x;
    const int tid = threadIdx.x;
#pragma unroll
    for (int pass = 0; pass < 2; pass++) {
        size_t idx = (size_t)n * QKVW + pass * 256 + tid;
        float x = qkv[idx];
        float p = x > 0.f ? x + 1.f : expf(x);
        float p2 = p * p;
#pragma unroll
        for (int o = 16; o; o >>= 1) p2 += __shfl_down_sync(0xffffffffu, p2, o);
        if ((tid & 31) == 0) wsum[tid >> 5] = p2;
        __syncthreads();
        int head = tid >> 6;
        float norm = sqrtf(wsum[head * 2] + wsum[head * 2 + 1]);
        qkv[idx] = p / (norm + EPSF);
        __syncthreads();
    }
}

// ---------------- per-chunk sums: S_c[j][dd] = sum_t v[t][j]*k[t][dd] ------
__global__ void __launch_bounds__(256) chunksum_kernel(
    const float* __restrict__ qkv, float* __restrict__ Sc, float* __restrict__ kcs)
{
    __shared__ float ks[64 * 64];
    __shared__ float vs[64 * 64];
    const int tid = threadIdx.x;
    const int c = blockIdx.x, bh = blockIdx.y;
    const int b = bh >> 2, h = bh & 3;
    const int nbase = b * TT + c * CHUNK;
    const int rowb = tid >> 4;
    const int dq = (tid & 15) * 4;
#pragma unroll
    for (int rep = 0; rep < 4; rep++) {
        int t = rowb + rep * 16;
        const float* src = qkv + (size_t)(nbase + t) * QKVW + h * 64 + dq;
        *(float4*)&ks[t * 64 + dq] = *(const float4*)(src + 256);
        *(float4*)&vs[t * 64 + dq] = *(const float4*)(src + 512);
    }
    __syncthreads();
    const int tx = tid & 15, ty = tid >> 4;
    float acc[4][4];
#pragma unroll
    for (int i = 0; i < 4; i++)
#pragma unroll
        for (int j = 0; j < 4; j++) acc[i][j] = 0.f;
    for (int t = 0; t < 64; t++) {
        float4 vv = *(const float4*)&vs[t * 64 + ty * 4];
        float4 kv = *(const float4*)&ks[t * 64 + tx * 4];
        float vm[4] = {vv.x, vv.y, vv.z, vv.w};
        float km[4] = {kv.x, kv.y, kv.z, kv.w};
#pragma unroll
        for (int i = 0; i < 4; i++)
#pragma unroll
            for (int j = 0; j < 4; j++)
                acc[i][j] += vm[i] * km[j];
    }
    size_t base = ((size_t)bh * NCH + c) * 4096;
#pragma unroll
    for (int i = 0; i < 4; i++) {
        float4 o = make_float4(acc[i][0], acc[i][1], acc[i][2], acc[i][3]);
        *(float4*)(Sc + base + (size_t)(ty * 4 + i) * 64 + tx * 4) = o;
    }
    if (tid < 64) {
        float s = 0.f;
        for (int t = 0; t < 64; t++) s += ks[t * 64 + tid];
        kcs[((size_t)bh * NCH + c) * 64 + tid] = s;
    }
}

// ---------------- exclusive prefix over chunks + final-state outputs -------
__global__ void __launch_bounds__(256) prefix_kernel(
    const float* __restrict__ Sc, const float* __restrict__ kcs,
    float* __restrict__ S0, float* __restrict__ kc0,
    float* __restrict__ dout, int out_size)
{
    const int tid = threadIdx.x;
    const int bh = blockIdx.y;
    const int e = blockIdx.x * 256 + tid;   // 0..4095
    float acc = 0.f;
    for (int c = 0; c < NCH; c++) {
        size_t idx = ((size_t)bh * NCH + c) * 4096 + e;
        S0[idx] = acc;
        acc += Sc[idx];
    }
    int kvoff = YSZ + bh * 4096 + e;
    if (kvoff < out_size) dout[kvoff] = acc;    // kv_f [B,H,j,d]
    if (blockIdx.x == 0 && tid < 64) {
        float a2 = 0.f;
        for (int c = 0; c < NCH; c++) {
            size_t idx = ((size_t)bh * NCH + c) * 64 + tid;
            kc0[idx] = a2;
            a2 += kcs[idx];
        }
        int kcoff = YSZ + KVSZ + bh * 64 + tid;
        if (kcoff < out_size) dout[kcoff] = a2; // kc_f [B,H,d]
    }
}

// ---------------- intra-chunk attention + state injection ------------------
// num = tril(QK^T)V + Q@S0 ; den = q.kc0 + rowsum(tril(QK^T)) + eps ; y=num/den
#define SMEM_INTRA (( (64*68)*3 + 64*64 + 64*68 + 64 + 64 ) * 4)
__global__ void __launch_bounds__(256) intra_kernel(
    const float* __restrict__ qkv, const float* __restrict__ S0g,
    const float* __restrict__ kc0g, float* __restrict__ y)
{
    extern __shared__ float sm[];
    float* Qt  = sm;               // [dd][t]  64x68 (transposed)
    float* Kt  = Qt + 64 * 68;     // [dd][t]  64x68
    float* St  = Kt + 64 * 68;     // [dd][j]  64x68 (S0 transposed)
    float* Vs  = St + 64 * 68;     // [t][j]   64x64
    float* Am  = Vs + 64 * 64;     // [r][c]   64x68
    float* kc0 = Am + 64 * 68;     // 64
    float* dens = kc0 + 64;        // 64

    const int tid = threadIdx.x;
    const int c = blockIdx.x, bh = blockIdx.y;
    const int b = bh >> 2, h = bh & 3;
    const int nbase = b * TT + c * CHUNK;
    const int rowb = tid >> 4;
    const int dq = (tid & 15) * 4;

    size_t s0base = ((size_t)bh * NCH + c) * 4096;
#pragma unroll
    for (int rep = 0; rep < 4; rep++) {
        int t = rowb + rep * 16;
        const float* src = qkv + (size_t)(nbase + t) * QKVW + h * 64 + dq;
        float4 q4 = *(const float4*)(src);
        float4 k4 = *(const float4*)(src + 256);
        float4 v4 = *(const float4*)(src + 512);
        Qt[(dq + 0) * 68 + t] = q4.x; Qt[(dq + 1) * 68 + t] = q4.y;
        Qt[(dq + 2) * 68 + t] = q4.z; Qt[(dq + 3) * 68 + t] = q4.w;
        Kt[(dq + 0) * 68 + t] = k4.x; Kt[(dq + 1) * 68 + t] = k4.y;
        Kt[(dq + 2) * 68 + t] = k4.z; Kt[(dq + 3) * 68 + t] = k4.w;
        *(float4*)&Vs[t * 64 + dq] = v4;
        float4 s4 = *(const float4*)(S0g + s0base + (size_t)t * 64 + dq);
        St[(dq + 0) * 68 + t] = s4.x; St[(dq + 1) * 68 + t] = s4.y;
        St[(dq + 2) * 68 + t] = s4.z; St[(dq + 3) * 68 + t] = s4.w;
    }
    if (tid < 64) kc0[tid] = kc0g[((size_t)bh * NCH + c) * 64 + tid];
    __syncthreads();

    const int tx = tid & 15, ty = tid >> 4;
    // A = Q K^T  (rows r = time within chunk, cols s = time within chunk)
    float a[4][4];
#pragma unroll
    for (int i = 0; i < 4; i++)
#pragma unroll
        for (int j = 0; j < 4; j++) a[i][j] = 0.f;
    for (int dd = 0; dd < 64; dd++) {
        float4 qv = *(const float4*)&Qt[dd * 68 + ty * 4];
        float4 kv = *(const float4*)&Kt[dd * 68 + tx * 4];
        float qm[4] = {qv.x, qv.y, qv.z, qv.w};
        float km[4] = {kv.x, kv.y, kv.z, kv.w};
#pragma unroll
        for (int i = 0; i < 4; i++)
#pragma unroll
            for (int j = 0; j < 4; j++)
                a[i][j] += qm[i] * km[j];
    }
    // causal mask (inclusive diagonal) into shared
#pragma unroll
    for (int i = 0; i < 4; i++) {
        int r = ty * 4 + i;
#pragma unroll
        for (int j = 0; j < 4; j++) {
            int cc = tx * 4 + j;
            Am[r * 68 + cc] = (cc <= r) ? a[i][j] : 0.f;
        }
    }
    __syncthreads();
    // den_r = eps + q_r . kc0 + rowsum(A_r)
    if (tid < 64) {
        int r = tid;
        float s = EPSF;
        for (int cc = 0; cc <= r; cc++) s += Am[r * 68 + cc];
        for (int dd = 0; dd < 64; dd++) s += Qt[dd * 68 + r] * kc0[dd];
        dens[r] = s;
    }
    __syncthreads();
    // num[r][j] = sum_c A[r][c]*V[c][j] + sum_dd Q[r][dd]*S0[j][dd]
    float acc[4][4];
#pragma unroll
    for (int i = 0; i < 4; i++)
#pragma unroll
        for (int j = 0; j < 4; j++) acc[i][j] = 0.f;
    for (int cc = 0; cc < 64; cc++) {
        float4 vv = *(const float4*)&Vs[cc * 64 + tx * 4];
        float vm[4] = {vv.x, vv.y, vv.z, vv.w};
        float am0 = Am[(ty * 4 + 0) * 68 + cc];
        float am1 = Am[(ty * 4 + 1) * 68 + cc];
        float am2 = Am[(ty * 4 + 2) * 68 + cc];
        float am3 = Am[(ty * 4 + 3) * 68 + cc];
        float amv[4] = {am0, am1, am2, am3};
#pragma unroll
        for (int i = 0; i < 4; i++)
#pragma unroll
            for (int j = 0; j < 4; j++)
                acc[i][j] += amv[i] * vm[j];
    }
    for (int dd = 0; dd < 64; dd++) {
        float4 qv = *(const float4*)&Qt[dd * 68 + ty * 4];
        float4 sv = *(const float4*)&St[dd * 68 + tx * 4];
        float qm[4] = {qv.x, qv.y, qv.z, qv.w};
        float smv[4] = {sv.x, sv.y, sv.z, sv.w};
#pragma unroll
        for (int i = 0; i < 4; i++)
#pragma unroll
            for (int j = 0; j < 4; j++)
                acc[i][j] += qm[i] * smv[j];
    }
#pragma unroll
    for (int i = 0; i < 4; i++) {
        int r = ty * 4 + i;
        float inv = 1.0f / dens[r];
        float4 o = make_float4(acc[i][0] * inv, acc[i][1] * inv,
                               acc[i][2] * inv, acc[i][3] * inv);
        *(float4*)(y + (size_t)(nbase + r) * 256 + h * 64 + tx * 4) = o;
    }
}

// ---------------------------------------------------------------------------
extern "C" void kernel_launch(void* const* d_in, const int* in_sizes, int n_in,
                              void* d_out, int out_size)
{
    const float* x  = (const float*)d_in[0];
    const float* Wq = (const float*)d_in[1];
    const float* Wk = (const float*)d_in[2];
    const float* Wv = (const float*)d_in[3];
    const float* Wo = (const float*)d_in[4];
    float* out = (float*)d_out;

    float *qkv, *y, *Sc, *S0, *kc, *kc0;
    cudaGetSymbolAddress((void**)&qkv, g_qkv);
    cudaGetSymbolAddress((void**)&y,   g_y);
    cudaGetSymbolAddress((void**)&Sc,  g_Sc);
    cudaGetSymbolAddress((void**)&S0,  g_S0);
    cudaGetSymbolAddress((void**)&kc,  g_kc);
    cudaGetSymbolAddress((void**)&kc0, g_kc0);

    cudaFuncSetAttribute(intra_kernel,
                         cudaFuncAttributeMaxDynamicSharedMemorySize, SMEM_INTRA);

    // QKV projection: 3 GEMMs into packed [token][768] buffer
    sgemm_tn<<<dim3(NTOK / 64, 4), 256>>>(x, DDIM, Wq, DDIM, qkv + 0,   QKVW, DDIM);
    sgemm_tn<<<dim3(NTOK / 64, 4), 256>>>(x, DDIM, Wk, DDIM, qkv + 256, QKVW, DDIM);
    sgemm_tn<<<dim3(NTOK / 64, 4), 256>>>(x, DDIM, Wv, DDIM, qkv + 512, QKVW, DDIM);

    // feature map on q,k
    posunit_kernel<<<NTOK, 256>>>(qkv);

    // chunked linear-attention scan
    chunksum_kernel<<<dim3(NCH, NBH), 256>>>(qkv, Sc, kc);
    prefix_kernel<<<dim3(16, NBH), 256>>>(Sc, kc, S0, kc0, out, out_size);
    intra_kernel<<<dim3(NCH, NBH), 256, SMEM_INTRA>>>(qkv, S0, kc0, y);

    // output projection into d_out (first 16.7M floats)
    sgemm_tn<<<dim3(NTOK / 64, DDIM / 64), 256>>>(y, 256, Wo, 256, out, DDIM, 256);
}

// round 3
// speedup vs baseline: 2.0890x; 2.0890x over previous
#include <cuda_runtime.h>
#include <cuda_bf16.h>
#include <cstdint>

#define EPSF 1e-6f

// Problem constants (B=4, T=4096, D=1024, H=4, d=64)
#define BB    4
#define TT    4096
#define DDIM  1024
#define HH    4
#define HD    64
#define NTOK  (BB*TT)        // 16384
#define QKVW  768
#define CHUNK 64
#define NCH   (TT/CHUNK)     // 64
#define NBH   (BB*HH)        // 16
#define YSZ   (16777216)     // NTOK*DDIM
#define KVSZ  (65536)        // NBH*64*64

// ---------------- scratch (device globals; no allocations allowed) ----------
__device__ __align__(128) float g_qkv[(size_t)NTOK * QKVW];        // 48 MB
__device__ __align__(128) float g_y  [(size_t)NTOK * 256];         // 16 MB
__device__ __align__(128) float g_Sc [(size_t)NBH * NCH * 4096];   // 16 MB
__device__ __align__(128) float g_S0 [(size_t)NBH * NCH * 4096];   // 16 MB
__device__ __align__(128) float g_kc [(size_t)NBH * NCH * 64];
__device__ __align__(128) float g_kc0[(size_t)NBH * NCH * 64];

// ======================= HMMA helpers (arch-neutral PTX) =====================
__device__ __forceinline__ uint32_t smem_to_u32(const void* p) {
    uint32_t a;
    asm("{ .reg .u64 t; cvta.to.shared.u64 t, %1; cvt.u32.u64 %0, t; }"
        : "=r"(a) : "l"(p));
    return a;
}

#define LDMX4(R, addr) \
    asm volatile("ldmatrix.sync.aligned.m8n8.x4.shared.b16 {%0,%1,%2,%3}, [%4];" \
        : "=r"((R)[0]), "=r"((R)[1]), "=r"((R)[2]), "=r"((R)[3]) : "r"(addr))

#define MMA_BF16(D, A, B) \
    asm volatile("mma.sync.aligned.m16n8k16.row.col.f32.bf16.bf16.f32 " \
        "{%0,%1,%2,%3},{%4,%5,%6,%7},{%8,%9},{%0,%1,%2,%3};" \
        : "+f"((D)[0]), "+f"((D)[1]), "+f"((D)[2]), "+f"((D)[3]) \
        : "r"((A)[0]), "r"((A)[1]), "r"((A)[2]), "r"((A)[3]), \
          "r"((B)[0]), "r"((B)[1]))

__device__ __forceinline__ uint32_t pack_bf16(float a, float b) {
    __nv_bfloat162 t;
    t.x = __float2bfloat16(a);
    t.y = __float2bfloat16(b);
    return *(uint32_t*)&t;
}

// split one float4 into hi/lo bf16 quads and store (8B each)
__device__ __forceinline__ void split_store(
    float4 v, __nv_bfloat16* hi, __nv_bfloat16* lo, uint32_t off)
{
    float hx = __bfloat162float(__float2bfloat16(v.x));
    float hy = __bfloat162float(__float2bfloat16(v.y));
    float hz = __bfloat162float(__float2bfloat16(v.z));
    float hw = __bfloat162float(__float2bfloat16(v.w));
    uint2 h = make_uint2(pack_bf16(v.x, v.y), pack_bf16(v.z, v.w));
    uint2 l = make_uint2(pack_bf16(v.x - hx, v.y - hy),
                         pack_bf16(v.z - hz, v.w - hw));
    *(uint2*)(hi + off) = h;
    *(uint2*)(lo + off) = l;
}

// ================== split-bf16 HMMA GEMM: C[m][n] = sum_k A[m][k]*B[n][k] ===
// 128x128 CTA tile, BK=32, 8 warps (2x4), warp tile 64x32.
// C = Ah*Bh + Ah*Bl + Al*Bh accumulated in fp32 registers.
#define LDS_A 40   // padded bf16 row stride (80B -> conflict-free ldmatrix)

__global__ void __launch_bounds__(256) hmma_gemm(
    const float* __restrict__ A, int lda,
    const float* __restrict__ B0, const float* __restrict__ B1,
    const float* __restrict__ B2, int bgroup, int ldb,
    float* __restrict__ C, int ldc, int K)
{
    __shared__ __align__(128) __nv_bfloat16 smA_h[128 * LDS_A];
    __shared__ __align__(128) __nv_bfloat16 smA_l[128 * LDS_A];
    __shared__ __align__(128) __nv_bfloat16 smB_h[128 * LDS_A];
    __shared__ __align__(128) __nv_bfloat16 smB_l[128 * LDS_A];

    const int tid = threadIdx.x;
    const int w = tid >> 5, lane = tid & 31;
    const int m0 = blockIdx.y * 128;
    const int n0 = blockIdx.x * 128;
    const int g = n0 / bgroup;
    const float* Bsrc = (g == 0) ? B0 : ((g == 1) ? B1 : B2);
    const int ncol = n0 - g * bgroup;

    // global prefetch coords: each thread loads 16 floats (4 float4) per tile
    const int lr = tid >> 1;            // row 0..127
    const int lc = (tid & 1) * 16;      // col 0 or 16
    const float* Ag = A + (size_t)(m0 + lr) * lda + lc;
    const float* Bg = Bsrc + (size_t)(ncol + lr) * ldb + lc;

    float4 pa[4], pb[4];
#pragma unroll
    for (int i = 0; i < 4; i++) {
        pa[i] = *(const float4*)(Ag + i * 4);
        pb[i] = *(const float4*)(Bg + i * 4);
    }

    float acc[4][4][4];
#pragma unroll
    for (int mt = 0; mt < 4; mt++)
#pragma unroll
        for (int nt = 0; nt < 4; nt++)
#pragma unroll
            for (int r = 0; r < 4; r++) acc[mt][nt][r] = 0.f;

    const uint32_t sAh = smem_to_u32(smA_h), sAl = smem_to_u32(smA_l);
    const uint32_t sBh = smem_to_u32(smB_h), sBl = smem_to_u32(smB_l);

    const int wm = w >> 2, wn = w & 3;
    // ldmatrix lane address components
    const int aRow = wm * 64 + (lane & 15);
    const int aCol = (lane >> 4) * 8;
    const int bRow = wn * 32 + (lane & 7) + ((lane >> 4) << 3);
    const int bCol = (lane & 8);

    const int NC = K / 32;
    for (int c = 0; c < NC; c++) {
        if (c) __syncthreads();
        // convert + stage current chunk
        const uint32_t soff = (uint32_t)lr * LDS_A + lc;
#pragma unroll
        for (int i = 0; i < 4; i++) {
            split_store(pa[i], smA_h, smA_l, soff + i * 4);
            split_store(pb[i], smB_h, smB_l, soff + i * 4);
        }
        __syncthreads();
        // prefetch next chunk (overlaps with MMA below)
        if (c + 1 < NC) {
#pragma unroll
            for (int i = 0; i < 4; i++) {
                pa[i] = *(const float4*)(Ag + (c + 1) * 32 + i * 4);
                pb[i] = *(const float4*)(Bg + (c + 1) * 32 + i * 4);
            }
        }
#pragma unroll
        for (int ks = 0; ks < 2; ks++) {
            const int kb = ks * 16;
            uint32_t bAddr = ((uint32_t)bRow * LDS_A + kb + bCol) * 2;
            uint32_t aAddr = ((uint32_t)aRow * LDS_A + kb + aCol) * 2;
            uint32_t bh[2][4], bl[2][4], af[4][4];
#pragma unroll
            for (int nt2 = 0; nt2 < 2; nt2++) {
                LDMX4(bh[nt2], sBh + bAddr + nt2 * (16 * LDS_A * 2));
                LDMX4(bl[nt2], sBl + bAddr + nt2 * (16 * LDS_A * 2));
            }
            // term 1+2: Ah*Bh, Ah*Bl
#pragma unroll
            for (int mt = 0; mt < 4; mt++)
                LDMX4(af[mt], sAh + aAddr + mt * (16 * LDS_A * 2));
#pragma unroll
            for (int mt = 0; mt < 4; mt++)
#pragma unroll
                for (int nt = 0; nt < 4; nt++)
                    MMA_BF16(acc[mt][nt], af[mt], &bh[nt >> 1][(nt & 1) * 2]);
#pragma unroll
            for (int mt = 0; mt < 4; mt++)
#pragma unroll
                for (int nt = 0; nt < 4; nt++)
                    MMA_BF16(acc[mt][nt], af[mt], &bl[nt >> 1][(nt & 1) * 2]);
            // term 3: Al*Bh
#pragma unroll
            for (int mt = 0; mt < 4; mt++)
                LDMX4(af[mt], sAl + aAddr + mt * (16 * LDS_A * 2));
#pragma unroll
            for (int mt = 0; mt < 4; mt++)
#pragma unroll
                for (int nt = 0; nt < 4; nt++)
                    MMA_BF16(acc[mt][nt], af[mt], &bh[nt >> 1][(nt & 1) * 2]);
        }
    }

    // epilogue: fragment owner writes fp32
    const int gr = lane >> 2, gc = (lane & 3) * 2;
#pragma unroll
    for (int mt = 0; mt < 4; mt++) {
#pragma unroll
        for (int nt = 0; nt < 4; nt++) {
            float* dst = C + (size_t)(m0 + wm * 64 + mt * 16 + gr) * ldc
                           + n0 + wn * 32 + nt * 8 + gc;
            *(float2*)dst = make_float2(acc[mt][nt][0], acc[mt][nt][1]);
            *(float2*)(dst + (size_t)8 * ldc) =
                make_float2(acc[mt][nt][2], acc[mt][nt][3]);
        }
    }
}

// ---------------- pos_unit: p = elu(x)+1; p /= (||p||_2 per head + eps) ----
__global__ void __launch_bounds__(256) posunit_kernel(float* __restrict__ qkv)
{
    __shared__ float wsum[8];
    const int n = blockIdx.x;
    const int tid = threadIdx.x;
#pragma unroll
    for (int pass = 0; pass < 2; pass++) {
        size_t idx = (size_t)n * QKVW + pass * 256 + tid;
        float x = qkv[idx];
        float p = x > 0.f ? x + 1.f : expf(x);
        float p2 = p * p;
#pragma unroll
        for (int o = 16; o; o >>= 1) p2 += __shfl_down_sync(0xffffffffu, p2, o);
        if ((tid & 31) == 0) wsum[tid >> 5] = p2;
        __syncthreads();
        int head = tid >> 6;
        float norm = sqrtf(wsum[head * 2] + wsum[head * 2 + 1]);
        qkv[idx] = p / (norm + EPSF);
        __syncthreads();
    }
}

// ---------------- per-chunk sums: S_c[j][dd] = sum_t v[t][j]*k[t][dd] ------
__global__ void __launch_bounds__(256) chunksum_kernel(
    const float* __restrict__ qkv, float* __restrict__ Sc, float* __restrict__ kcs)
{
    __shared__ float ks[64 * 64];
    __shared__ float vs[64 * 64];
    const int tid = threadIdx.x;
    const int c = blockIdx.x, bh = blockIdx.y;
    const int b = bh >> 2, h = bh & 3;
    const int nbase = b * TT + c * CHUNK;
    const int rowb = tid >> 4;
    const int dq = (tid & 15) * 4;
#pragma unroll
    for (int rep = 0; rep < 4; rep++) {
        int t = rowb + rep * 16;
        const float* src = qkv + (size_t)(nbase + t) * QKVW + h * 64 + dq;
        *(float4*)&ks[t * 64 + dq] = *(const float4*)(src + 256);
        *(float4*)&vs[t * 64 + dq] = *(const float4*)(src + 512);
    }
    __syncthreads();
    const int tx = tid & 15, ty = tid >> 4;
    float acc[4][4];
#pragma unroll
    for (int i = 0; i < 4; i++)
#pragma unroll
        for (int j = 0; j < 4; j++) acc[i][j] = 0.f;
    for (int t = 0; t < 64; t++) {
        float4 vv = *(const float4*)&vs[t * 64 + ty * 4];
        float4 kv = *(const float4*)&ks[t * 64 + tx * 4];
        float vm[4] = {vv.x, vv.y, vv.z, vv.w};
        float km[4] = {kv.x, kv.y, kv.z, kv.w};
#pragma unroll
        for (int i = 0; i < 4; i++)
#pragma unroll
            for (int j = 0; j < 4; j++)
                acc[i][j] += vm[i] * km[j];
    }
    size_t base = ((size_t)bh * NCH + c) * 4096;
#pragma unroll
    for (int i = 0; i < 4; i++) {
        float4 o = make_float4(acc[i][0], acc[i][1], acc[i][2], acc[i][3]);
        *(float4*)(Sc + base + (size_t)(ty * 4 + i) * 64 + tx * 4) = o;
    }
    if (tid < 64) {
        float s = 0.f;
        for (int t = 0; t < 64; t++) s += ks[t * 64 + tid];
        kcs[((size_t)bh * NCH + c) * 64 + tid] = s;
    }
}

// ---------------- exclusive prefix over chunks + final-state outputs -------
__global__ void __launch_bounds__(256) prefix_kernel(
    const float* __restrict__ Sc, const float* __restrict__ kcs,
    float* __restrict__ S0, float* __restrict__ kc0,
    float* __restrict__ dout, int out_size)
{
    const int tid = threadIdx.x;
    const int bh = blockIdx.y;
    const int e = blockIdx.x * 256 + tid;   // 0..4095
    float acc = 0.f;
    for (int c = 0; c < NCH; c++) {
        size_t idx = ((size_t)bh * NCH + c) * 4096 + e;
        S0[idx] = acc;
        acc += Sc[idx];
    }
    int kvoff = YSZ + bh * 4096 + e;
    if (kvoff < out_size) dout[kvoff] = acc;    // kv_f [B,H,j,d]
    if (blockIdx.x == 0 && tid < 64) {
        float a2 = 0.f;
        for (int c = 0; c < NCH; c++) {
            size_t idx = ((size_t)bh * NCH + c) * 64 + tid;
            kc0[idx] = a2;
            a2 += kcs[idx];
        }
        int kcoff = YSZ + KVSZ + bh * 64 + tid;
        if (kcoff < out_size) dout[kcoff] = a2; // kc_f [B,H,d]
    }
}

// ---------------- intra-chunk attention + state injection ------------------
#define SMEM_INTRA (( (64*68)*3 + 64*64 + 64*68 + 64 + 64 ) * 4)
__global__ void __launch_bounds__(256) intra_kernel(
    const float* __restrict__ qkv, const float* __restrict__ S0g,
    const float* __restrict__ kc0g, float* __restrict__ y)
{
    extern __shared__ float smf[];
    float* Qt  = smf;              // [dd][t]  64x68 (transposed)
    float* Kt  = Qt + 64 * 68;     // [dd][t]  64x68
    float* St  = Kt + 64 * 68;     // [dd][j]  64x68 (S0 transposed)
    float* Vs  = St + 64 * 68;     // [t][j]   64x64
    float* Am  = Vs + 64 * 64;     // [r][c]   64x68
    float* kc0 = Am + 64 * 68;     // 64
    float* dens = kc0 + 64;        // 64

    const int tid = threadIdx.x;
    const int c = blockIdx.x, bh = blockIdx.y;
    const int b = bh >> 2, h = bh & 3;
    const int nbase = b * TT + c * CHUNK;
    const int rowb = tid >> 4;
    const int dq = (tid & 15) * 4;

    size_t s0base = ((size_t)bh * NCH + c) * 4096;
#pragma unroll
    for (int rep = 0; rep < 4; rep++) {
        int t = rowb + rep * 16;
        const float* src = qkv + (size_t)(nbase + t) * QKVW + h * 64 + dq;
        float4 q4 = *(const float4*)(src);
        float4 k4 = *(const float4*)(src + 256);
        float4 v4 = *(const float4*)(src + 512);
        Qt[(dq + 0) * 68 + t] = q4.x; Qt[(dq + 1) * 68 + t] = q4.y;
        Qt[(dq + 2) * 68 + t] = q4.z; Qt[(dq + 3) * 68 + t] = q4.w;
        Kt[(dq + 0) * 68 + t] = k4.x; Kt[(dq + 1) * 68 + t] = k4.y;
        Kt[(dq + 2) * 68 + t] = k4.z; Kt[(dq + 3) * 68 + t] = k4.w;
        *(float4*)&Vs[t * 64 + dq] = v4;
        float4 s4 = *(const float4*)(S0g + s0base + (size_t)t * 64 + dq);
        St[(dq + 0) * 68 + t] = s4.x; St[(dq + 1) * 68 + t] = s4.y;
        St[(dq + 2) * 68 + t] = s4.z; St[(dq + 3) * 68 + t] = s4.w;
    }
    if (tid < 64) kc0[tid] = kc0g[((size_t)bh * NCH + c) * 64 + tid];
    __syncthreads();

    const int tx = tid & 15, ty = tid >> 4;
    float a[4][4];
#pragma unroll
    for (int i = 0; i < 4; i++)
#pragma unroll
        for (int j = 0; j < 4; j++) a[i][j] = 0.f;
    for (int dd = 0; dd < 64; dd++) {
        float4 qv = *(const float4*)&Qt[dd * 68 + ty * 4];
        float4 kv = *(const float4*)&Kt[dd * 68 + tx * 4];
        float qm[4] = {qv.x, qv.y, qv.z, qv.w};
        float km[4] = {kv.x, kv.y, kv.z, kv.w};
#pragma unroll
        for (int i = 0; i < 4; i++)
#pragma unroll
            for (int j = 0; j < 4; j++)
                a[i][j] += qm[i] * km[j];
    }
#pragma unroll
    for (int i = 0; i < 4; i++) {
        int r = ty * 4 + i;
#pragma unroll
        for (int j = 0; j < 4; j++) {
            int cc = tx * 4 + j;
            Am[r * 68 + cc] = (cc <= r) ? a[i][j] : 0.f;
        }
    }
    __syncthreads();
    if (tid < 64) {
        int r = tid;
        float s = EPSF;
        for (int cc = 0; cc <= r; cc++) s += Am[r * 68 + cc];
        for (int dd = 0; dd < 64; dd++) s += Qt[dd * 68 + r] * kc0[dd];
        dens[r] = s;
    }
    __syncthreads();
    float acc[4][4];
#pragma unroll
    for (int i = 0; i < 4; i++)
#pragma unroll
        for (int j = 0; j < 4; j++) acc[i][j] = 0.f;
    for (int cc = 0; cc < 64; cc++) {
        float4 vv = *(const float4*)&Vs[cc * 64 + tx * 4];
        float vm[4] = {vv.x, vv.y, vv.z, vv.w};
        float amv[4] = {Am[(ty * 4 + 0) * 68 + cc], Am[(ty * 4 + 1) * 68 + cc],
                        Am[(ty * 4 + 2) * 68 + cc], Am[(ty * 4 + 3) * 68 + cc]};
#pragma unroll
        for (int i = 0; i < 4; i++)
#pragma unroll
            for (int j = 0; j < 4; j++)
                acc[i][j] += amv[i] * vm[j];
    }
    for (int dd = 0; dd < 64; dd++) {
        float4 qv = *(const float4*)&Qt[dd * 68 + ty * 4];
        float4 sv = *(const float4*)&St[dd * 68 + tx * 4];
        float qm[4] = {qv.x, qv.y, qv.z, qv.w};
        float smv[4] = {sv.x, sv.y, sv.z, sv.w};
#pragma unroll
        for (int i = 0; i < 4; i++)
#pragma unroll
            for (int j = 0; j < 4; j++)
                acc[i][j] += qm[i] * smv[j];
    }
#pragma unroll
    for (int i = 0; i < 4; i++) {
        int r = ty * 4 + i;
        float inv = 1.0f / dens[r];
        float4 o = make_float4(acc[i][0] * inv, acc[i][1] * inv,
                               acc[i][2] * inv, acc[i][3] * inv);
        *(float4*)(y + (size_t)(nbase + r) * 256 + h * 64 + tx * 4) = o;
    }
}

// ---------------------------------------------------------------------------
extern "C" void kernel_launch(void* const* d_in, const int* in_sizes, int n_in,
                              void* d_out, int out_size)
{
    const float* x  = (const float*)d_in[0];
    const float* Wq = (const float*)d_in[1];
    const float* Wk = (const float*)d_in[2];
    const float* Wv = (const float*)d_in[3];
    const float* Wo = (const float*)d_in[4];
    float* out = (float*)d_out;

    float *qkv, *y, *Sc, *S0, *kc, *kc0;
    cudaGetSymbolAddress((void**)&qkv, g_qkv);
    cudaGetSymbolAddress((void**)&y,   g_y);
    cudaGetSymbolAddress((void**)&Sc,  g_Sc);
    cudaGetSymbolAddress((void**)&S0,  g_S0);
    cudaGetSymbolAddress((void**)&kc,  g_kc);
    cudaGetSymbolAddress((void**)&kc0, g_kc0);

    cudaFuncSetAttribute(intra_kernel,
                         cudaFuncAttributeMaxDynamicSharedMemorySize, SMEM_INTRA);

    // QKV projection (HMMA split-bf16): qkv[t][0:768] = x @ [Wq;Wk;Wv]^T
    hmma_gemm<<<dim3(6, NTOK / 128), 256>>>(
        x, DDIM, Wq, Wk, Wv, 256, DDIM, qkv, QKVW, DDIM);

    // feature map on q,k
    posunit_kernel<<<NTOK, 256>>>(qkv);

    // chunked linear-attention scan
    chunksum_kernel<<<dim3(NCH, NBH), 256>>>(qkv, Sc, kc);
    prefix_kernel<<<dim3(16, NBH), 256>>>(Sc, kc, S0, kc0, out, out_size);
    intra_kernel<<<dim3(NCH, NBH), 256, SMEM_INTRA>>>(qkv, S0, kc0, y);

    // output projection (HMMA split-bf16): out = y @ Wo^T
    hmma_gemm<<<dim3(8, NTOK / 128), 256>>>(
        y, 256, Wo, Wo, Wo, 1 << 30, 256, out, DDIM, 256);
}

// round 4
// speedup vs baseline: 2.5341x; 1.2130x over previous
#include <cuda_runtime.h>
#include <cuda_bf16.h>
#include <cstdint>

#define EPSF 1e-6f

// Problem constants (B=4, T=4096, D=1024, H=4, d=64)
#define BB    4
#define TT    4096
#define DDIM  1024
#define HH    4
#define HD    64
#define NTOK  (BB*TT)        // 16384
#define QKVW  768
#define CHUNK 64
#define NCH   (TT/CHUNK)     // 64
#define NBH   (BB*HH)        // 16
#define YSZ   (16777216)     // NTOK*DDIM
#define KVSZ  (65536)        // NBH*64*64

// ---------------- scratch (device globals; no allocations allowed) ----------
__device__ __align__(128) float g_qkv[(size_t)NTOK * QKVW];          // 48 MB
__device__ __align__(128) float g_Sc [(size_t)NBH * NCH * 4096];     // 16 MB
__device__ __align__(128) float g_S0 [(size_t)NBH * NCH * 4096];     // 16 MB
__device__ __align__(128) float g_kc [(size_t)NBH * NCH * 64];
__device__ __align__(128) float g_kc0[(size_t)NBH * NCH * 64];
// split-bf16 operand copies
__device__ __align__(128) __nv_bfloat16 g_xh[(size_t)NTOK * DDIM];   // 32 MB
__device__ __align__(128) __nv_bfloat16 g_xl[(size_t)NTOK * DDIM];   // 32 MB
__device__ __align__(128) __nv_bfloat16 g_Wh[(size_t)QKVW * DDIM];   // 1.5 MB
__device__ __align__(128) __nv_bfloat16 g_Wl[(size_t)QKVW * DDIM];
__device__ __align__(128) __nv_bfloat16 g_Woh[(size_t)DDIM * 256];
__device__ __align__(128) __nv_bfloat16 g_Wol[(size_t)DDIM * 256];
__device__ __align__(128) __nv_bfloat16 g_yh[(size_t)NTOK * 256];    // 8 MB
__device__ __align__(128) __nv_bfloat16 g_yl[(size_t)NTOK * 256];    // 8 MB

// ======================= PTX helpers (arch-neutral) =========================
__device__ __forceinline__ uint32_t smem_to_u32(const void* p) {
    uint32_t a;
    asm("{ .reg .u64 t; cvta.to.shared.u64 t, %1; cvt.u32.u64 %0, t; }"
        : "=r"(a) : "l"(p));
    return a;
}
#define LDMX4(R, addr) \
    asm volatile("ldmatrix.sync.aligned.m8n8.x4.shared.b16 {%0,%1,%2,%3}, [%4];" \
        : "=r"((R)[0]), "=r"((R)[1]), "=r"((R)[2]), "=r"((R)[3]) : "r"(addr))
#define MMA_BF16(D, A, B) \
    asm volatile("mma.sync.aligned.m16n8k16.row.col.f32.bf16.bf16.f32 " \
        "{%0,%1,%2,%3},{%4,%5,%6,%7},{%8,%9},{%0,%1,%2,%3};" \
        : "+f"((D)[0]), "+f"((D)[1]), "+f"((D)[2]), "+f"((D)[3]) \
        : "r"((A)[0]), "r"((A)[1]), "r"((A)[2]), "r"((A)[3]), \
          "r"((B)[0]), "r"((B)[1]))
__device__ __forceinline__ void cpa16(uint32_t dst, const void* src) {
    asm volatile("cp.async.cg.shared.global [%0], [%1], 16;"
                 :: "r"(dst), "l"(src) : "memory");
}
#define CPA_COMMIT() asm volatile("cp.async.commit_group;" ::: "memory")
#define CPA_WAIT1()  asm volatile("cp.async.wait_group 1;"  ::: "memory")

__device__ __forceinline__ uint32_t pack_bf16(float a, float b) {
    __nv_bfloat162 t;
    t.x = __float2bfloat16(a);
    t.y = __float2bfloat16(b);
    return *(uint32_t*)&t;
}
__device__ __forceinline__ void split4(float4 v, uint2& h, uint2& l) {
    float hx = __bfloat162float(__float2bfloat16(v.x));
    float hy = __bfloat162float(__float2bfloat16(v.y));
    float hz = __bfloat162float(__float2bfloat16(v.z));
    float hw = __bfloat162float(__float2bfloat16(v.w));
    h = make_uint2(pack_bf16(v.x, v.y), pack_bf16(v.z, v.w));
    l = make_uint2(pack_bf16(v.x - hx, v.y - hy), pack_bf16(v.z - hz, v.w - hw));
}

// ---------------- fp32 -> (hi, lo) bf16 elementwise split -------------------
__global__ void __launch_bounds__(256) convert_split(
    const float4* __restrict__ src, uint2* __restrict__ dh,
    uint2* __restrict__ dl, int n4)
{
    int i = blockIdx.x * 256 + threadIdx.x;
    if (i < n4) {
        uint2 h, l;
        split4(src[i], h, l);
        dh[i] = h;
        dl[i] = l;
    }
}

// ================== split-bf16 HMMA GEMM (precomputed operands) =============
// C[m][n] = sum_k A[m][k]*B[n][k]; A,B given as hi/lo bf16; C fp32.
// 128x128 CTA tile, BK=32, cp.async double buffer, 8 warps (2x4), warp 64x32.
#define LDS_A   40
#define TILE_B  (128 * LDS_A * 2)   // 10240 B per bf16 tile
#define STAGE_B (4 * TILE_B)        // Ah Al Bh Bl
#define GEMM_SMEM (2 * STAGE_B)     // 81920 B

__global__ void __launch_bounds__(256) hmma_gemm_bf(
    const __nv_bfloat16* __restrict__ Ah, const __nv_bfloat16* __restrict__ Al,
    int lda,
    const __nv_bfloat16* __restrict__ Bh, const __nv_bfloat16* __restrict__ Bl,
    int ldb,
    float* __restrict__ C, int ldc, int K)
{
    extern __shared__ __align__(128) char smem[];
    const uint32_t sbase = smem_to_u32(smem);
    const int tid = threadIdx.x;
    const int w = tid >> 5, lane = tid & 31;
    const int m0 = blockIdx.y * 128;
    const int n0 = blockIdx.x * 128;

    // cp.async thread mapping: 2 x 16B per tile per thread
    const int row0 = tid >> 2, c16 = tid & 3;          // id = tid
    const int row1 = (tid + 256) >> 2;                 // id = tid + 256 (same c16)
    const uint32_t d0 = (uint32_t)row0 * (LDS_A * 2) + c16 * 16;
    const uint32_t d1 = (uint32_t)row1 * (LDS_A * 2) + c16 * 16;
    const size_t aoff0 = (size_t)(m0 + row0) * lda + c16 * 8;
    const size_t aoff1 = (size_t)(m0 + row1) * lda + c16 * 8;
    const size_t boff0 = (size_t)(n0 + row0) * ldb + c16 * 8;
    const size_t boff1 = (size_t)(n0 + row1) * ldb + c16 * 8;

    float acc[4][4][4];
#pragma unroll
    for (int mt = 0; mt < 4; mt++)
#pragma unroll
        for (int nt = 0; nt < 4; nt++)
#pragma unroll
            for (int r = 0; r < 4; r++) acc[mt][nt][r] = 0.f;

    const int wm = w >> 2, wn = w & 3;
    const int aRow = wm * 64 + (lane & 15);
    const int aCol = (lane >> 4) * 8;
    const int bRow = wn * 32 + (lane & 7) + ((lane >> 4) << 3);
    const int bCol = (lane & 8);

    const int NC = K / 32;

    // prologue: stage 0 loads chunk 0
    {
        const int koff = 0;
        uint32_t sb = sbase;
        cpa16(sb + 0 * TILE_B + d0, Ah + aoff0 + koff);
        cpa16(sb + 0 * TILE_B + d1, Ah + aoff1 + koff);
        cpa16(sb + 1 * TILE_B + d0, Al + aoff0 + koff);
        cpa16(sb + 1 * TILE_B + d1, Al + aoff1 + koff);
        cpa16(sb + 2 * TILE_B + d0, Bh + boff0 + koff);
        cpa16(sb + 2 * TILE_B + d1, Bh + boff1 + koff);
        cpa16(sb + 3 * TILE_B + d0, Bl + boff0 + koff);
        cpa16(sb + 3 * TILE_B + d1, Bl + boff1 + koff);
        CPA_COMMIT();
    }

    for (int c = 0; c < NC; c++) {
        // issue loads for chunk c+1 into the other stage
        if (c + 1 < NC) {
            const int koff = (c + 1) * 32;
            uint32_t sb = sbase + ((c + 1) & 1) * STAGE_B;
            cpa16(sb + 0 * TILE_B + d0, Ah + aoff0 + koff);
            cpa16(sb + 0 * TILE_B + d1, Ah + aoff1 + koff);
            cpa16(sb + 1 * TILE_B + d0, Al + aoff0 + koff);
            cpa16(sb + 1 * TILE_B + d1, Al + aoff1 + koff);
            cpa16(sb + 2 * TILE_B + d0, Bh + boff0 + koff);
            cpa16(sb + 2 * TILE_B + d1, Bh + boff1 + koff);
            cpa16(sb + 3 * TILE_B + d0, Bl + boff0 + koff);
            cpa16(sb + 3 * TILE_B + d1, Bl + boff1 + koff);
        }
        CPA_COMMIT();
        CPA_WAIT1();        // chunk c's stage resident
        __syncthreads();

        const uint32_t st = sbase + (c & 1) * STAGE_B;
        const uint32_t sAh = st, sAl = st + TILE_B;
        const uint32_t sBh = st + 2 * TILE_B, sBl = st + 3 * TILE_B;
#pragma unroll
        for (int ks = 0; ks < 2; ks++) {
            const int kb = ks * 16;
            uint32_t bAddr = ((uint32_t)bRow * LDS_A + kb + bCol) * 2;
            uint32_t aAddr = ((uint32_t)aRow * LDS_A + kb + aCol) * 2;
            uint32_t bh[2][4], bl[2][4], af[4][4];
#pragma unroll
            for (int nt2 = 0; nt2 < 2; nt2++) {
                LDMX4(bh[nt2], sBh + bAddr + nt2 * (16 * LDS_A * 2));
                LDMX4(bl[nt2], sBl + bAddr + nt2 * (16 * LDS_A * 2));
            }
#pragma unroll
            for (int mt = 0; mt < 4; mt++)
                LDMX4(af[mt], sAh + aAddr + mt * (16 * LDS_A * 2));
#pragma unroll
            for (int mt = 0; mt < 4; mt++)
#pragma unroll
                for (int nt = 0; nt < 4; nt++)
                    MMA_BF16(acc[mt][nt], af[mt], &bh[nt >> 1][(nt & 1) * 2]);
#pragma unroll
            for (int mt = 0; mt < 4; mt++)
#pragma unroll
                for (int nt = 0; nt < 4; nt++)
                    MMA_BF16(acc[mt][nt], af[mt], &bl[nt >> 1][(nt & 1) * 2]);
#pragma unroll
            for (int mt = 0; mt < 4; mt++)
                LDMX4(af[mt], sAl + aAddr + mt * (16 * LDS_A * 2));
#pragma unroll
            for (int mt = 0; mt < 4; mt++)
#pragma unroll
                for (int nt = 0; nt < 4; nt++)
                    MMA_BF16(acc[mt][nt], af[mt], &bh[nt >> 1][(nt & 1) * 2]);
        }
        __syncthreads();   // all warps done with stage (c&1) before overwrite
    }

    // epilogue
    const int gr = lane >> 2, gc = (lane & 3) * 2;
#pragma unroll
    for (int mt = 0; mt < 4; mt++) {
#pragma unroll
        for (int nt = 0; nt < 4; nt++) {
            float* dst = C + (size_t)(m0 + wm * 64 + mt * 16 + gr) * ldc
                           + n0 + wn * 32 + nt * 8 + gc;
            *(float2*)dst = make_float2(acc[mt][nt][0], acc[mt][nt][1]);
            *(float2*)(dst + (size_t)8 * ldc) =
                make_float2(acc[mt][nt][2], acc[mt][nt][3]);
        }
    }
}

// ---------------- fused pos_unit helper (per 4 elems, 16-lane row groups) ---
__device__ __forceinline__ float4 posunit4(float4 v) {
    float4 p;
    p.x = v.x > 0.f ? v.x + 1.f : __expf(v.x);
    p.y = v.y > 0.f ? v.y + 1.f : __expf(v.y);
    p.z = v.z > 0.f ? v.z + 1.f : __expf(v.z);
    p.w = v.w > 0.f ? v.w + 1.f : __expf(v.w);
    float s = p.x * p.x + p.y * p.y + p.z * p.z + p.w * p.w;
    s += __shfl_xor_sync(0xffffffffu, s, 8);
    s += __shfl_xor_sync(0xffffffffu, s, 4);
    s += __shfl_xor_sync(0xffffffffu, s, 2);
    s += __shfl_xor_sync(0xffffffffu, s, 1);
    float inv = 1.0f / (sqrtf(s) + EPSF);
    p.x *= inv; p.y *= inv; p.z *= inv; p.w *= inv;
    return p;
}

// ---------------- per-chunk sums (posunit fused on k) -----------------------
__global__ void __launch_bounds__(256) chunksum_kernel(
    const float* __restrict__ qkv, float* __restrict__ Sc, float* __restrict__ kcs)
{
    __shared__ float ks[64 * 64];
    __shared__ float vs[64 * 64];
    const int tid = threadIdx.x;
    const int c = blockIdx.x, bh = blockIdx.y;
    const int b = bh >> 2, h = bh & 3;
    const int nbase = b * TT + c * CHUNK;
    const int rowb = tid >> 4;
    const int dq = (tid & 15) * 4;
#pragma unroll
    for (int rep = 0; rep < 4; rep++) {
        int t = rowb + rep * 16;
        const float* src = qkv + (size_t)(nbase + t) * QKVW + h * 64 + dq;
        float4 k4 = posunit4(*(const float4*)(src + 256));
        *(float4*)&ks[t * 64 + dq] = k4;
        *(float4*)&vs[t * 64 + dq] = *(const float4*)(src + 512);
    }
    __syncthreads();
    const int tx = tid & 15, ty = tid >> 4;
    float acc[4][4];
#pragma unroll
    for (int i = 0; i < 4; i++)
#pragma unroll
        for (int j = 0; j < 4; j++) acc[i][j] = 0.f;
    for (int t = 0; t < 64; t++) {
        float4 vv = *(const float4*)&vs[t * 64 + ty * 4];
        float4 kv = *(const float4*)&ks[t * 64 + tx * 4];
        float vm[4] = {vv.x, vv.y, vv.z, vv.w};
        float km[4] = {kv.x, kv.y, kv.z, kv.w};
#pragma unroll
        for (int i = 0; i < 4; i++)
#pragma unroll
            for (int j = 0; j < 4; j++)
                acc[i][j] += vm[i] * km[j];
    }
    size_t base = ((size_t)bh * NCH + c) * 4096;
#pragma unroll
    for (int i = 0; i < 4; i++) {
        float4 o = make_float4(acc[i][0], acc[i][1], acc[i][2], acc[i][3]);
        *(float4*)(Sc + base + (size_t)(ty * 4 + i) * 64 + tx * 4) = o;
    }
    if (tid < 64) {
        float s = 0.f;
        for (int t = 0; t < 64; t++) s += ks[t * 64 + tid];
        kcs[((size_t)bh * NCH + c) * 64 + tid] = s;
    }
}

// ---------------- exclusive prefix over chunks + final-state outputs -------
__global__ void __launch_bounds__(256) prefix_kernel(
    const float* __restrict__ Sc, const float* __restrict__ kcs,
    float* __restrict__ S0, float* __restrict__ kc0,
    float* __restrict__ dout, int out_size)
{
    const int tid = threadIdx.x;
    const int bh = blockIdx.y;
    const int e = blockIdx.x * 256 + tid;   // 0..4095
    float acc = 0.f;
    for (int c = 0; c < NCH; c++) {
        size_t idx = ((size_t)bh * NCH + c) * 4096 + e;
        S0[idx] = acc;
        acc += Sc[idx];
    }
    int kvoff = YSZ + bh * 4096 + e;
    if (kvoff < out_size) dout[kvoff] = acc;    // kv_f [B,H,j,d]
    if (blockIdx.x == 0 && tid < 64) {
        float a2 = 0.f;
        for (int c = 0; c < NCH; c++) {
            size_t idx = ((size_t)bh * NCH + c) * 64 + tid;
            kc0[idx] = a2;
            a2 += kcs[idx];
        }
        int kcoff = YSZ + KVSZ + bh * 64 + tid;
        if (kcoff < out_size) dout[kcoff] = a2; // kc_f [B,H,d]
    }
}

// ---------------- intra-chunk attention (posunit fused; y -> split bf16) ---
#define SMEM_INTRA (( (64*68)*3 + 64*64 + 64*68 + 64 + 64 ) * 4)
__global__ void __launch_bounds__(256) intra_kernel(
    const float* __restrict__ qkv, const float* __restrict__ S0g,
    const float* __restrict__ kc0g,
    __nv_bfloat16* __restrict__ yh, __nv_bfloat16* __restrict__ yl)
{
    extern __shared__ float smf[];
    float* Qt  = smf;              // [dd][t]  64x68 (transposed)
    float* Kt  = Qt + 64 * 68;     // [dd][t]  64x68
    float* St  = Kt + 64 * 68;     // [dd][j]  64x68 (S0 transposed)
    float* Vs  = St + 64 * 68;     // [t][j]   64x64
    float* Am  = Vs + 64 * 64;     // [r][c]   64x68
    float* kc0 = Am + 64 * 68;     // 64
    float* dens = kc0 + 64;        // 64

    const int tid = threadIdx.x;
    const int c = blockIdx.x, bh = blockIdx.y;
    const int b = bh >> 2, h = bh & 3;
    const int nbase = b * TT + c * CHUNK;
    const int rowb = tid >> 4;
    const int dq = (tid & 15) * 4;

    size_t s0base = ((size_t)bh * NCH + c) * 4096;
#pragma unroll
    for (int rep = 0; rep < 4; rep++) {
        int t = rowb + rep * 16;
        const float* src = qkv + (size_t)(nbase + t) * QKVW + h * 64 + dq;
        float4 q4 = posunit4(*(const float4*)(src));
        float4 k4 = posunit4(*(const float4*)(src + 256));
        float4 v4 = *(const float4*)(src + 512);
        Qt[(dq + 0) * 68 + t] = q4.x; Qt[(dq + 1) * 68 + t] = q4.y;
        Qt[(dq + 2) * 68 + t] = q4.z; Qt[(dq + 3) * 68 + t] = q4.w;
        Kt[(dq + 0) * 68 + t] = k4.x; Kt[(dq + 1) * 68 + t] = k4.y;
        Kt[(dq + 2) * 68 + t] = k4.z; Kt[(dq + 3) * 68 + t] = k4.w;
        *(float4*)&Vs[t * 64 + dq] = v4;
        float4 s4 = *(const float4*)(S0g + s0base + (size_t)t * 64 + dq);
        St[(dq + 0) * 68 + t] = s4.x; St[(dq + 1) * 68 + t] = s4.y;
        St[(dq + 2) * 68 + t] = s4.z; St[(dq + 3) * 68 + t] = s4.w;
    }
    if (tid < 64) kc0[tid] = kc0g[((size_t)bh * NCH + c) * 64 + tid];
    __syncthreads();

    const int tx = tid & 15, ty = tid >> 4;
    float a[4][4];
#pragma unroll
    for (int i = 0; i < 4; i++)
#pragma unroll
        for (int j = 0; j < 4; j++) a[i][j] = 0.f;
    for (int dd = 0; dd < 64; dd++) {
        float4 qv = *(const float4*)&Qt[dd * 68 + ty * 4];
        float4 kv = *(const float4*)&Kt[dd * 68 + tx * 4];
        float qm[4] = {qv.x, qv.y, qv.z, qv.w};
        float km[4] = {kv.x, kv.y, kv.z, kv.w};
#pragma unroll
        for (int i = 0; i < 4; i++)
#pragma unroll
            for (int j = 0; j < 4; j++)
                a[i][j] += qm[i] * km[j];
    }
#pragma unroll
    for (int i = 0; i < 4; i++) {
        int r = ty * 4 + i;
#pragma unroll
        for (int j = 0; j < 4; j++) {
            int cc = tx * 4 + j;
            Am[r * 68 + cc] = (cc <= r) ? a[i][j] : 0.f;
        }
    }
    __syncthreads();
    if (tid < 64) {
        int r = tid;
        float s = EPSF;
        for (int cc = 0; cc <= r; cc++) s += Am[r * 68 + cc];
        for (int dd = 0; dd < 64; dd++) s += Qt[dd * 68 + r] * kc0[dd];
        dens[r] = s;
    }
    __syncthreads();
    float acc[4][4];
#pragma unroll
    for (int i = 0; i < 4; i++)
#pragma unroll
        for (int j = 0; j < 4; j++) acc[i][j] = 0.f;
    for (int cc = 0; cc < 64; cc++) {
        float4 vv = *(const float4*)&Vs[cc * 64 + tx * 4];
        float vm[4] = {vv.x, vv.y, vv.z, vv.w};
        float amv[4] = {Am[(ty * 4 + 0) * 68 + cc], Am[(ty * 4 + 1) * 68 + cc],
                        Am[(ty * 4 + 2) * 68 + cc], Am[(ty * 4 + 3) * 68 + cc]};
#pragma unroll
        for (int i = 0; i < 4; i++)
#pragma unroll
            for (int j = 0; j < 4; j++)
                acc[i][j] += amv[i] * vm[j];
    }
    for (int dd = 0; dd < 64; dd++) {
        float4 qv = *(const float4*)&Qt[dd * 68 + ty * 4];
        float4 sv = *(const float4*)&St[dd * 68 + tx * 4];
        float qm[4] = {qv.x, qv.y, qv.z, qv.w};
        float smv[4] = {sv.x, sv.y, sv.z, sv.w};
#pragma unroll
        for (int i = 0; i < 4; i++)
#pragma unroll
            for (int j = 0; j < 4; j++)
                acc[i][j] += qm[i] * smv[j];
    }
#pragma unroll
    for (int i = 0; i < 4; i++) {
        int r = ty * 4 + i;
        float inv = 1.0f / dens[r];
        float4 o = make_float4(acc[i][0] * inv, acc[i][1] * inv,
                               acc[i][2] * inv, acc[i][3] * inv);
        uint2 hbits, lbits;
        split4(o, hbits, lbits);
        size_t off = (size_t)(nbase + r) * 256 + h * 64 + tx * 4;
        *(uint2*)(yh + off) = hbits;
        *(uint2*)(yl + off) = lbits;
    }
}

// ---------------------------------------------------------------------------
extern "C" void kernel_launch(void* const* d_in, const int* in_sizes, int n_in,
                              void* d_out, int out_size)
{
    const float* x  = (const float*)d_in[0];
    const float* Wq = (const float*)d_in[1];
    const float* Wk = (const float*)d_in[2];
    const float* Wv = (const float*)d_in[3];
    const float* Wo = (const float*)d_in[4];
    float* out = (float*)d_out;

    float *qkv, *Sc, *S0, *kc, *kc0;
    __nv_bfloat16 *xh, *xl, *Wh, *Wl, *Woh, *Wol, *yh, *yl;
    cudaGetSymbolAddress((void**)&qkv, g_qkv);
    cudaGetSymbolAddress((void**)&Sc,  g_Sc);
    cudaGetSymbolAddress((void**)&S0,  g_S0);
    cudaGetSymbolAddress((void**)&kc,  g_kc);
    cudaGetSymbolAddress((void**)&kc0, g_kc0);
    cudaGetSymbolAddress((void**)&xh,  g_xh);
    cudaGetSymbolAddress((void**)&xl,  g_xl);
    cudaGetSymbolAddress((void**)&Wh,  g_Wh);
    cudaGetSymbolAddress((void**)&Wl,  g_Wl);
    cudaGetSymbolAddress((void**)&Woh, g_Woh);
    cudaGetSymbolAddress((void**)&Wol, g_Wol);
    cudaGetSymbolAddress((void**)&yh,  g_yh);
    cudaGetSymbolAddress((void**)&yl,  g_yl);

    cudaFuncSetAttribute(intra_kernel,
                         cudaFuncAttributeMaxDynamicSharedMemorySize, SMEM_INTRA);
    cudaFuncSetAttribute(hmma_gemm_bf,
                         cudaFuncAttributeMaxDynamicSharedMemorySize, GEMM_SMEM);

    // split-precision operand preparation (one pass each)
    convert_split<<<(NTOK * DDIM / 4 + 255) / 256, 256>>>(
        (const float4*)x, (uint2*)xh, (uint2*)xl, NTOK * DDIM / 4);
    convert_split<<<(256 * DDIM / 4 + 255) / 256, 256>>>(
        (const float4*)Wq, (uint2*)Wh, (uint2*)Wl, 256 * DDIM / 4);
    convert_split<<<(256 * DDIM / 4 + 255) / 256, 256>>>(
        (const float4*)Wk, (uint2*)(Wh + 256 * DDIM), (uint2*)(Wl + 256 * DDIM),
        256 * DDIM / 4);
    convert_split<<<(256 * DDIM / 4 + 255) / 256, 256>>>(
        (const float4*)Wv, (uint2*)(Wh + 512 * DDIM), (uint2*)(Wl + 512 * DDIM),
        256 * DDIM / 4);
    convert_split<<<(DDIM * 256 / 4 + 255) / 256, 256>>>(
        (const float4*)Wo, (uint2*)Woh, (uint2*)Wol, DDIM * 256 / 4);

    // QKV projection: qkv[t][0:768] = x @ [Wq;Wk;Wv]^T
    hmma_gemm_bf<<<dim3(6, NTOK / 128), 256, GEMM_SMEM>>>(
        xh, xl, DDIM, Wh, Wl, DDIM, qkv, QKVW, DDIM);

    // chunked linear-attention scan (posunit fused into consumers)
    chunksum_kernel<<<dim3(NCH, NBH), 256>>>(qkv, Sc, kc);
    prefix_kernel<<<dim3(16, NBH), 256>>>(Sc, kc, S0, kc0, out, out_size);
    intra_kernel<<<dim3(NCH, NBH), 256, SMEM_INTRA>>>(qkv, S0, kc0, yh, yl);

    // output projection: out = y @ Wo^T
    hmma_gemm_bf<<<dim3(8, NTOK / 128), 256, GEMM_SMEM>>>(
        yh, yl, 256, Woh, Wol, 256, out, DDIM, 256);
}

// round 5
// speedup vs baseline: 3.0873x; 1.2183x over previous
#include <cuda_runtime.h>
#include <cuda_fp16.h>
#include <cstdint>

#define EPSF 1e-6f

// Problem constants (B=4, T=4096, D=1024, H=4, d=64)
#define BB    4
#define TT    4096
#define DDIM  1024
#define HH    4
#define HD    64
#define NTOK  (BB*TT)        // 16384
#define QKVW  768
#define CHUNK 64
#define NCH   (TT/CHUNK)     // 64
#define NBH   (BB*HH)        // 16
#define YSZ   (16777216)     // NTOK*DDIM
#define KVSZ  (65536)        // NBH*64*64

// ---------------- scratch (device globals; no allocations allowed) ----------
__device__ __align__(128) float g_qkv[(size_t)NTOK * QKVW];          // 48 MB
__device__ __align__(128) float g_Sc [(size_t)NBH * NCH * 4096];     // 16 MB
__device__ __align__(128) float g_S0 [(size_t)NBH * NCH * 4096];     // 16 MB
__device__ __align__(128) float g_kc [(size_t)NBH * NCH * 64];
__device__ __align__(128) float g_kc0[(size_t)NBH * NCH * 64];
// split-fp16 operand copies
__device__ __align__(128) __half g_xh[(size_t)NTOK * DDIM];          // 32 MB
__device__ __align__(128) __half g_xl[(size_t)NTOK * DDIM];          // 32 MB
__device__ __align__(128) __half g_Wh[(size_t)QKVW * DDIM];          // 1.5 MB
__device__ __align__(128) __half g_Woh[(size_t)DDIM * 256];
__device__ __align__(128) __half g_yh[(size_t)NTOK * 256];           // 8 MB
__device__ __align__(128) __half g_yl[(size_t)NTOK * 256];           // 8 MB

// ======================= PTX helpers (arch-neutral) =========================
__device__ __forceinline__ uint32_t smem_to_u32(const void* p) {
    uint32_t a;
    asm("{ .reg .u64 t; cvta.to.shared.u64 t, %1; cvt.u32.u64 %0, t; }"
        : "=r"(a) : "l"(p));
    return a;
}
#define LDMX4(R, addr) \
    asm volatile("ldmatrix.sync.aligned.m8n8.x4.shared.b16 {%0,%1,%2,%3}, [%4];" \
        : "=r"((R)[0]), "=r"((R)[1]), "=r"((R)[2]), "=r"((R)[3]) : "r"(addr))
#define MMA_FP16(D, A, B) \
    asm volatile("mma.sync.aligned.m16n8k16.row.col.f32.f16.f16.f32 " \
        "{%0,%1,%2,%3},{%4,%5,%6,%7},{%8,%9},{%0,%1,%2,%3};" \
        : "+f"((D)[0]), "+f"((D)[1]), "+f"((D)[2]), "+f"((D)[3]) \
        : "r"((A)[0]), "r"((A)[1]), "r"((A)[2]), "r"((A)[3]), \
          "r"((B)[0]), "r"((B)[1]))
__device__ __forceinline__ void cpa16(uint32_t dst, const void* src) {
    asm volatile("cp.async.cg.shared.global [%0], [%1], 16;"
                 :: "r"(dst), "l"(src) : "memory");
}
#define CPA_COMMIT() asm volatile("cp.async.commit_group;" ::: "memory")
#define CPA_WAIT1()  asm volatile("cp.async.wait_group 1;"  ::: "memory")

__device__ __forceinline__ uint32_t pack_h(float a, float b) {
    __half2 t;
    t.x = __float2half_rn(a);
    t.y = __float2half_rn(b);
    return *(uint32_t*)&t;
}
// exact fp16 (hi, lo) split of a float4
__device__ __forceinline__ void split4h(float4 v, uint2& h, uint2& l) {
    float hx = __half2float(__float2half_rn(v.x));
    float hy = __half2float(__float2half_rn(v.y));
    float hz = __half2float(__float2half_rn(v.z));
    float hw = __half2float(__float2half_rn(v.w));
    h = make_uint2(pack_h(v.x, v.y), pack_h(v.z, v.w));
    l = make_uint2(pack_h(v.x - hx, v.y - hy), pack_h(v.z - hz, v.w - hw));
}

// ---------------- fp32 -> (hi, lo) fp16 split ------------------------------
__global__ void __launch_bounds__(256) convert_split(
    const float4* __restrict__ src, uint2* __restrict__ dh,
    uint2* __restrict__ dl, int n4)
{
    int i = blockIdx.x * 256 + threadIdx.x;
    if (i < n4) {
        uint2 h, l;
        split4h(src[i], h, l);
        dh[i] = h;
        dl[i] = l;
    }
}
// ---------------- fp32 -> fp16 round (single) ------------------------------
__global__ void __launch_bounds__(256) convert_round(
    const float4* __restrict__ src, uint2* __restrict__ dh, int n4)
{
    int i = blockIdx.x * 256 + threadIdx.x;
    if (i < n4) {
        float4 v = src[i];
        dh[i] = make_uint2(pack_h(v.x, v.y), pack_h(v.z, v.w));
    }
}

// ============ split-fp16 HMMA GEMM: C = (Ah+Al) @ Bh^T ======================
// 128x128 CTA tile, BK=32, cp.async double buffer, 8 warps (2x4), warp 64x32.
// 2 CTAs/SM.
#define LDS_A   40
#define TILE_B  (128 * LDS_A * 2)   // 10240 B per fp16 tile
#define STAGE_B (3 * TILE_B)        // Ah Al Bh
#define GEMM_SMEM (2 * STAGE_B)     // 61440 B

__global__ void __launch_bounds__(256, 2) hmma_gemm_fp16(
    const __half* __restrict__ Ah, const __half* __restrict__ Al, int lda,
    const __half* __restrict__ Bh, int ldb,
    float* __restrict__ C, int ldc, int K)
{
    extern __shared__ __align__(128) char smem[];
    const uint32_t sbase = smem_to_u32(smem);
    const int tid = threadIdx.x;
    const int w = tid >> 5, lane = tid & 31;
    const int m0 = blockIdx.y * 128;
    const int n0 = blockIdx.x * 128;

    // cp.async mapping: per tile, 256 threads x 2 rows of 16B
    const int row0 = tid >> 2, c16 = tid & 3;
    const int row1 = (tid + 256) >> 2;
    const uint32_t d0 = (uint32_t)row0 * (LDS_A * 2) + c16 * 16;
    const uint32_t d1 = (uint32_t)row1 * (LDS_A * 2) + c16 * 16;
    const size_t aoff0 = (size_t)(m0 + row0) * lda + c16 * 8;
    const size_t aoff1 = (size_t)(m0 + row1) * lda + c16 * 8;
    const size_t boff0 = (size_t)(n0 + row0) * ldb + c16 * 8;
    const size_t boff1 = (size_t)(n0 + row1) * ldb + c16 * 8;

    float acc[4][4][4];
#pragma unroll
    for (int mt = 0; mt < 4; mt++)
#pragma unroll
        for (int nt = 0; nt < 4; nt++)
#pragma unroll
            for (int r = 0; r < 4; r++) acc[mt][nt][r] = 0.f;

    const int wm = w >> 2, wn = w & 3;
    const int aRow = wm * 64 + (lane & 15);
    const int aCol = (lane >> 4) * 8;
    const int bRow = wn * 32 + (lane & 7) + ((lane >> 4) << 3);
    const int bCol = (lane & 8);

    const int NC = K / 32;

    // prologue: stage 0 <- chunk 0
    {
        uint32_t sb = sbase;
        cpa16(sb + 0 * TILE_B + d0, Ah + aoff0);
        cpa16(sb + 0 * TILE_B + d1, Ah + aoff1);
        cpa16(sb + 1 * TILE_B + d0, Al + aoff0);
        cpa16(sb + 1 * TILE_B + d1, Al + aoff1);
        cpa16(sb + 2 * TILE_B + d0, Bh + boff0);
        cpa16(sb + 2 * TILE_B + d1, Bh + boff1);
        CPA_COMMIT();
    }

    for (int c = 0; c < NC; c++) {
        if (c + 1 < NC) {
            const int koff = (c + 1) * 32;
            uint32_t sb = sbase + ((c + 1) & 1) * STAGE_B;
            cpa16(sb + 0 * TILE_B + d0, Ah + aoff0 + koff);
            cpa16(sb + 0 * TILE_B + d1, Ah + aoff1 + koff);
            cpa16(sb + 1 * TILE_B + d0, Al + aoff0 + koff);
            cpa16(sb + 1 * TILE_B + d1, Al + aoff1 + koff);
            cpa16(sb + 2 * TILE_B + d0, Bh + boff0 + koff);
            cpa16(sb + 2 * TILE_B + d1, Bh + boff1 + koff);
        }
        CPA_COMMIT();
        CPA_WAIT1();
        __syncthreads();

        const uint32_t st = sbase + (c & 1) * STAGE_B;
        const uint32_t sAh = st, sAl = st + TILE_B, sB = st + 2 * TILE_B;
#pragma unroll
        for (int ks = 0; ks < 2; ks++) {
            const int kb = ks * 16;
            uint32_t bAddr = ((uint32_t)bRow * LDS_A + kb + bCol) * 2;
            uint32_t aAddr = ((uint32_t)aRow * LDS_A + kb + aCol) * 2;
            uint32_t bf[2][4], af[4][4];
#pragma unroll
            for (int nt2 = 0; nt2 < 2; nt2++)
                LDMX4(bf[nt2], sB + bAddr + nt2 * (16 * LDS_A * 2));
#pragma unroll
            for (int mt = 0; mt < 4; mt++)
                LDMX4(af[mt], sAh + aAddr + mt * (16 * LDS_A * 2));
#pragma unroll
            for (int mt = 0; mt < 4; mt++)
#pragma unroll
                for (int nt = 0; nt < 4; nt++)
                    MMA_FP16(acc[mt][nt], af[mt], &bf[nt >> 1][(nt & 1) * 2]);
#pragma unroll
            for (int mt = 0; mt < 4; mt++)
                LDMX4(af[mt], sAl + aAddr + mt * (16 * LDS_A * 2));
#pragma unroll
            for (int mt = 0; mt < 4; mt++)
#pragma unroll
                for (int nt = 0; nt < 4; nt++)
                    MMA_FP16(acc[mt][nt], af[mt], &bf[nt >> 1][(nt & 1) * 2]);
        }
        __syncthreads();
    }

    // epilogue
    const int gr = lane >> 2, gc = (lane & 3) * 2;
#pragma unroll
    for (int mt = 0; mt < 4; mt++) {
#pragma unroll
        for (int nt = 0; nt < 4; nt++) {
            float* dst = C + (size_t)(m0 + wm * 64 + mt * 16 + gr) * ldc
                           + n0 + wn * 32 + nt * 8 + gc;
            *(float2*)dst = make_float2(acc[mt][nt][0], acc[mt][nt][1]);
            *(float2*)(dst + (size_t)8 * ldc) =
                make_float2(acc[mt][nt][2], acc[mt][nt][3]);
        }
    }
}

// ---------------- fused pos_unit helper (per 4 elems, 16-lane row groups) ---
__device__ __forceinline__ float4 posunit4(float4 v) {
    float4 p;
    p.x = v.x > 0.f ? v.x + 1.f : __expf(v.x);
    p.y = v.y > 0.f ? v.y + 1.f : __expf(v.y);
    p.z = v.z > 0.f ? v.z + 1.f : __expf(v.z);
    p.w = v.w > 0.f ? v.w + 1.f : __expf(v.w);
    float s = p.x * p.x + p.y * p.y + p.z * p.z + p.w * p.w;
    s += __shfl_xor_sync(0xffffffffu, s, 8);
    s += __shfl_xor_sync(0xffffffffu, s, 4);
    s += __shfl_xor_sync(0xffffffffu, s, 2);
    s += __shfl_xor_sync(0xffffffffu, s, 1);
    float inv = 1.0f / (sqrtf(s) + EPSF);
    p.x *= inv; p.y *= inv; p.z *= inv; p.w *= inv;
    return p;
}

// ---------------- per-chunk sums (posunit fused on k) -----------------------
__global__ void __launch_bounds__(256) chunksum_kernel(
    const float* __restrict__ qkv, float* __restrict__ Sc, float* __restrict__ kcs)
{
    __shared__ float ks[64 * 64];
    __shared__ float vs[64 * 64];
    const int tid = threadIdx.x;
    const int c = blockIdx.x, bh = blockIdx.y;
    const int b = bh >> 2, h = bh & 3;
    const int nbase = b * TT + c * CHUNK;
    const int rowb = tid >> 4;
    const int dq = (tid & 15) * 4;
#pragma unroll
    for (int rep = 0; rep < 4; rep++) {
        int t = rowb + rep * 16;
        const float* src = qkv + (size_t)(nbase + t) * QKVW + h * 64 + dq;
        float4 k4 = posunit4(*(const float4*)(src + 256));
        *(float4*)&ks[t * 64 + dq] = k4;
        *(float4*)&vs[t * 64 + dq] = *(const float4*)(src + 512);
    }
    __syncthreads();
    const int tx = tid & 15, ty = tid >> 4;
    float acc[4][4];
#pragma unroll
    for (int i = 0; i < 4; i++)
#pragma unroll
        for (int j = 0; j < 4; j++) acc[i][j] = 0.f;
    for (int t = 0; t < 64; t++) {
        float4 vv = *(const float4*)&vs[t * 64 + ty * 4];
        float4 kv = *(const float4*)&ks[t * 64 + tx * 4];
        float vm[4] = {vv.x, vv.y, vv.z, vv.w};
        float km[4] = {kv.x, kv.y, kv.z, kv.w};
#pragma unroll
        for (int i = 0; i < 4; i++)
#pragma unroll
            for (int j = 0; j < 4; j++)
                acc[i][j] += vm[i] * km[j];
    }
    size_t base = ((size_t)bh * NCH + c) * 4096;
#pragma unroll
    for (int i = 0; i < 4; i++) {
        float4 o = make_float4(acc[i][0], acc[i][1], acc[i][2], acc[i][3]);
        *(float4*)(Sc + base + (size_t)(ty * 4 + i) * 64 + tx * 4) = o;
    }
    if (tid < 64) {
        float s = 0.f;
        for (int t = 0; t < 64; t++) s += ks[t * 64 + tid];
        kcs[((size_t)bh * NCH + c) * 64 + tid] = s;
    }
}

// ---------------- exclusive prefix over chunks + final-state outputs -------
__global__ void __launch_bounds__(256) prefix_kernel(
    const float* __restrict__ Sc, const float* __restrict__ kcs,
    float* __restrict__ S0, float* __restrict__ kc0,
    float* __restrict__ dout, int out_size)
{
    const int tid = threadIdx.x;
    const int bh = blockIdx.y;
    const int e = blockIdx.x * 256 + tid;   // 0..4095
    float acc = 0.f;
    for (int c = 0; c < NCH; c++) {
        size_t idx = ((size_t)bh * NCH + c) * 4096 + e;
        S0[idx] = acc;
        acc += Sc[idx];
    }
    int kvoff = YSZ + bh * 4096 + e;
    if (kvoff < out_size) dout[kvoff] = acc;    // kv_f [B,H,j,d]
    if (blockIdx.x == 0 && tid < 64) {
        float a2 = 0.f;
        for (int c = 0; c < NCH; c++) {
            size_t idx = ((size_t)bh * NCH + c) * 64 + tid;
            kc0[idx] = a2;
            a2 += kcs[idx];
        }
        int kcoff = YSZ + KVSZ + bh * 64 + tid;
        if (kcoff < out_size) dout[kcoff] = a2; // kc_f [B,H,d]
    }
}

// ---------------- intra-chunk attention (posunit fused; y -> split fp16) ---
#define SMEM_INTRA (( (64*68)*3 + 64*64 + 64*68 + 64 + 64 ) * 4)
__global__ void __launch_bounds__(256) intra_kernel(
    const float* __restrict__ qkv, const float* __restrict__ S0g,
    const float* __restrict__ kc0g,
    __half* __restrict__ yh, __half* __restrict__ yl)
{
    extern __shared__ float smf[];
    float* Qt  = smf;              // [dd][t]  64x68 (transposed)
    float* Kt  = Qt + 64 * 68;     // [dd][t]  64x68
    float* St  = Kt + 64 * 68;     // [dd][j]  64x68 (S0 transposed)
    float* Vs  = St + 64 * 68;     // [t][j]   64x64
    float* Am  = Vs + 64 * 64;     // [r][c]   64x68
    float* kc0 = Am + 64 * 68;     // 64
    float* dens = kc0 + 64;        // 64

    const int tid = threadIdx.x;
    const int c = blockIdx.x, bh = blockIdx.y;
    const int b = bh >> 2, h = bh & 3;
    const int nbase = b * TT + c * CHUNK;
    const int rowb = tid >> 4;
    const int dq = (tid & 15) * 4;

    size_t s0base = ((size_t)bh * NCH + c) * 4096;
#pragma unroll
    for (int rep = 0; rep < 4; rep++) {
        int t = rowb + rep * 16;
        const float* src = qkv + (size_t)(nbase + t) * QKVW + h * 64 + dq;
        float4 q4 = posunit4(*(const float4*)(src));
        float4 k4 = posunit4(*(const float4*)(src + 256));
        float4 v4 = *(const float4*)(src + 512);
        Qt[(dq + 0) * 68 + t] = q4.x; Qt[(dq + 1) * 68 + t] = q4.y;
        Qt[(dq + 2) * 68 + t] = q4.z; Qt[(dq + 3) * 68 + t] = q4.w;
        Kt[(dq + 0) * 68 + t] = k4.x; Kt[(dq + 1) * 68 + t] = k4.y;
        Kt[(dq + 2) * 68 + t] = k4.z; Kt[(dq + 3) * 68 + t] = k4.w;
        *(float4*)&Vs[t * 64 + dq] = v4;
        float4 s4 = *(const float4*)(S0g + s0base + (size_t)t * 64 + dq);
        St[(dq + 0) * 68 + t] = s4.x; St[(dq + 1) * 68 + t] = s4.y;
        St[(dq + 2) * 68 + t] = s4.z; St[(dq + 3) * 68 + t] = s4.w;
    }
    if (tid < 64) kc0[tid] = kc0g[((size_t)bh * NCH + c) * 64 + tid];
    __syncthreads();

    const int tx = tid & 15, ty = tid >> 4;
    float a[4][4];
#pragma unroll
    for (int i = 0; i < 4; i++)
#pragma unroll
        for (int j = 0; j < 4; j++) a[i][j] = 0.f;
    for (int dd = 0; dd < 64; dd++) {
        float4 qv = *(const float4*)&Qt[dd * 68 + ty * 4];
        float4 kv = *(const float4*)&Kt[dd * 68 + tx * 4];
        float qm[4] = {qv.x, qv.y, qv.z, qv.w};
        float km[4] = {kv.x, kv.y, kv.z, kv.w};
#pragma unroll
        for (int i = 0; i < 4; i++)
#pragma unroll
            for (int j = 0; j < 4; j++)
                a[i][j] += qm[i] * km[j];
    }
#pragma unroll
    for (int i = 0; i < 4; i++) {
        int r = ty * 4 + i;
#pragma unroll
        for (int j = 0; j < 4; j++) {
            int cc = tx * 4 + j;
            Am[r * 68 + cc] = (cc <= r) ? a[i][j] : 0.f;
        }
    }
    __syncthreads();
    if (tid < 64) {
        int r = tid;
        float s = EPSF;
        for (int cc = 0; cc <= r; cc++) s += Am[r * 68 + cc];
        for (int dd = 0; dd < 64; dd++) s += Qt[dd * 68 + r] * kc0[dd];
        dens[r] = s;
    }
    __syncthreads();
    float acc[4][4];
#pragma unroll
    for (int i = 0; i < 4; i++)
#pragma unroll
        for (int j = 0; j < 4; j++) acc[i][j] = 0.f;
    for (int cc = 0; cc < 64; cc++) {
        float4 vv = *(const float4*)&Vs[cc * 64 + tx * 4];
        float vm[4] = {vv.x, vv.y, vv.z, vv.w};
        float amv[4] = {Am[(ty * 4 + 0) * 68 + cc], Am[(ty * 4 + 1) * 68 + cc],
                        Am[(ty * 4 + 2) * 68 + cc], Am[(ty * 4 + 3) * 68 + cc]};
#pragma unroll
        for (int i = 0; i < 4; i++)
#pragma unroll
            for (int j = 0; j < 4; j++)
                acc[i][j] += amv[i] * vm[j];
    }
    for (int dd = 0; dd < 64; dd++) {
        float4 qv = *(const float4*)&Qt[dd * 68 + ty * 4];
        float4 sv = *(const float4*)&St[dd * 68 + tx * 4];
        float qm[4] = {qv.x, qv.y, qv.z, qv.w};
        float smv[4] = {sv.x, sv.y, sv.z, sv.w};
#pragma unroll
        for (int i = 0; i < 4; i++)
#pragma unroll
            for (int j = 0; j < 4; j++)
                acc[i][j] += qm[i] * smv[j];
    }
#pragma unroll
    for (int i = 0; i < 4; i++) {
        int r = ty * 4 + i;
        float inv = 1.0f / dens[r];
        float4 o = make_float4(acc[i][0] * inv, acc[i][1] * inv,
                               acc[i][2] * inv, acc[i][3] * inv);
        uint2 hbits, lbits;
        split4h(o, hbits, lbits);
        size_t off = (size_t)(nbase + r) * 256 + h * 64 + tx * 4;
        *(uint2*)(yh + off) = hbits;
        *(uint2*)(yl + off) = lbits;
    }
}

// ---------------------------------------------------------------------------
extern "C" void kernel_launch(void* const* d_in, const int* in_sizes, int n_in,
                              void* d_out, int out_size)
{
    const float* x  = (const float*)d_in[0];
    const float* Wq = (const float*)d_in[1];
    const float* Wk = (const float*)d_in[2];
    const float* Wv = (const float*)d_in[3];
    const float* Wo = (const float*)d_in[4];
    float* out = (float*)d_out;

    float *qkv, *Sc, *S0, *kc, *kc0;
    __half *xh, *xl, *Wh, *Woh, *yh, *yl;
    cudaGetSymbolAddress((void**)&qkv, g_qkv);
    cudaGetSymbolAddress((void**)&Sc,  g_Sc);
    cudaGetSymbolAddress((void**)&S0,  g_S0);
    cudaGetSymbolAddress((void**)&kc,  g_kc);
    cudaGetSymbolAddress((void**)&kc0, g_kc0);
    cudaGetSymbolAddress((void**)&xh,  g_xh);
    cudaGetSymbolAddress((void**)&xl,  g_xl);
    cudaGetSymbolAddress((void**)&Wh,  g_Wh);
    cudaGetSymbolAddress((void**)&Woh, g_Woh);
    cudaGetSymbolAddress((void**)&yh,  g_yh);
    cudaGetSymbolAddress((void**)&yl,  g_yl);

    cudaFuncSetAttribute(intra_kernel,
                         cudaFuncAttributeMaxDynamicSharedMemorySize, SMEM_INTRA);
    cudaFuncSetAttribute(hmma_gemm_fp16,
                         cudaFuncAttributeMaxDynamicSharedMemorySize, GEMM_SMEM);

    // operand preparation: x -> exact fp16 pair; weights -> single fp16
    convert_split<<<(NTOK * DDIM / 4 + 255) / 256, 256>>>(
        (const float4*)x, (uint2*)xh, (uint2*)xl, NTOK * DDIM / 4);
    convert_round<<<(256 * DDIM / 4 + 255) / 256, 256>>>(
        (const float4*)Wq, (uint2*)Wh, 256 * DDIM / 4);
    convert_round<<<(256 * DDIM / 4 + 255) / 256, 256>>>(
        (const float4*)Wk, (uint2*)(Wh + 256 * DDIM), 256 * DDIM / 4);
    convert_round<<<(256 * DDIM / 4 + 255) / 256, 256>>>(
        (const float4*)Wv, (uint2*)(Wh + 512 * DDIM), 256 * DDIM / 4);
    convert_round<<<(DDIM * 256 / 4 + 255) / 256, 256>>>(
        (const float4*)Wo, (uint2*)Woh, DDIM * 256 / 4);

    // QKV projection: qkv[t][0:768] = x @ [Wq;Wk;Wv]^T
    hmma_gemm_fp16<<<dim3(6, NTOK / 128), 256, GEMM_SMEM>>>(
        xh, xl, DDIM, Wh, DDIM, qkv, QKVW, DDIM);

    // chunked linear-attention scan (posunit fused into consumers)
    chunksum_kernel<<<dim3(NCH, NBH), 256>>>(qkv, Sc, kc);
    prefix_kernel<<<dim3(16, NBH), 256>>>(Sc, kc, S0, kc0, out, out_size);
    intra_kernel<<<dim3(NCH, NBH), 256, SMEM_INTRA>>>(qkv, S0, kc0, yh, yl);

    // output projection: out = y @ Wo^T
    hmma_gemm_fp16<<<dim3(8, NTOK / 128), 256, GEMM_SMEM>>>(
        yh, yl, 256, Woh, 256, out, DDIM, 256);
}

// round 6
// speedup vs baseline: 3.1832x; 1.0311x over previous
#include <cuda_runtime.h>
#include <cuda_fp16.h>
#include <cstdint>

#define EPSF 1e-6f

// Problem constants (B=4, T=4096, D=1024, H=4, d=64)
#define BB    4
#define TT    4096
#define DDIM  1024
#define HH    4
#define HD    64
#define NTOK  (BB*TT)        // 16384
#define QKVW  768
#define CHUNK 64
#define NCH   (TT/CHUNK)     // 64
#define NBH   (BB*HH)        // 16
#define YSZ   (16777216)     // NTOK*DDIM
#define KVSZ  (65536)        // NBH*64*64

// ---------------- scratch (device globals; no allocations allowed) ----------
__device__ __align__(128) float g_qkv[(size_t)NTOK * QKVW];          // 48 MB
__device__ __align__(128) float g_Sc [(size_t)NBH * NCH * 4096];     // 16 MB
__device__ __align__(128) float g_S0 [(size_t)NBH * NCH * 4096];     // 16 MB
__device__ __align__(128) float g_kc [(size_t)NBH * NCH * 64];
__device__ __align__(128) float g_kc0[(size_t)NBH * NCH * 64];
// split-fp16 operand copies
__device__ __align__(128) __half g_xh[(size_t)NTOK * DDIM];          // 32 MB
__device__ __align__(128) __half g_xl[(size_t)NTOK * DDIM];          // 32 MB
__device__ __align__(128) __half g_Wh[(size_t)QKVW * DDIM];          // 1.5 MB
__device__ __align__(128) __half g_Woh[(size_t)DDIM * 256];
__device__ __align__(128) __half g_yh[(size_t)NTOK * 256];           // 8 MB
__device__ __align__(128) __half g_yl[(size_t)NTOK * 256];           // 8 MB

// ======================= PTX helpers (arch-neutral) =========================
__device__ __forceinline__ uint32_t smem_to_u32(const void* p) {
    uint32_t a;
    asm("{ .reg .u64 t; cvta.to.shared.u64 t, %1; cvt.u32.u64 %0, t; }"
        : "=r"(a) : "l"(p));
    return a;
}
#define LDMX4(R, addr) \
    asm volatile("ldmatrix.sync.aligned.m8n8.x4.shared.b16 {%0,%1,%2,%3}, [%4];" \
        : "=r"((R)[0]), "=r"((R)[1]), "=r"((R)[2]), "=r"((R)[3]) : "r"(addr))
#define MMA_FP16(D, A, B) \
    asm volatile("mma.sync.aligned.m16n8k16.row.col.f32.f16.f16.f32 " \
        "{%0,%1,%2,%3},{%4,%5,%6,%7},{%8,%9},{%0,%1,%2,%3};" \
        : "+f"((D)[0]), "+f"((D)[1]), "+f"((D)[2]), "+f"((D)[3]) \
        : "r"((A)[0]), "r"((A)[1]), "r"((A)[2]), "r"((A)[3]), \
          "r"((B)[0]), "r"((B)[1]))
__device__ __forceinline__ void cpa16(uint32_t dst, const void* src) {
    asm volatile("cp.async.cg.shared.global [%0], [%1], 16;"
                 :: "r"(dst), "l"(src) : "memory");
}
#define CPA_COMMIT() asm volatile("cp.async.commit_group;" ::: "memory")
#define CPA_WAIT1()  asm volatile("cp.async.wait_group 1;"  ::: "memory")

__device__ __forceinline__ uint32_t pack_h(float a, float b) {
    __half2 t;
    t.x = __float2half_rn(a);
    t.y = __float2half_rn(b);
    return *(uint32_t*)&t;
}
// exact fp16 (hi, lo) split of a float4
__device__ __forceinline__ void split4h(float4 v, uint2& h, uint2& l) {
    float hx = __half2float(__float2half_rn(v.x));
    float hy = __half2float(__float2half_rn(v.y));
    float hz = __half2float(__float2half_rn(v.z));
    float hw = __half2float(__float2half_rn(v.w));
    h = make_uint2(pack_h(v.x, v.y), pack_h(v.z, v.w));
    l = make_uint2(pack_h(v.x - hx, v.y - hy), pack_h(v.z - hz, v.w - hw));
}

// ---------------- fp32 -> (hi, lo) fp16 split (x) --------------------------
__global__ void __launch_bounds__(256) convert_split(
    const float4* __restrict__ src, uint2* __restrict__ dh,
    uint2* __restrict__ dl, int n4)
{
    int i = blockIdx.x * 256 + threadIdx.x;
    if (i < n4) {
        uint2 h, l;
        split4h(src[i], h, l);
        dh[i] = h;
        dl[i] = l;
    }
}
// ---------------- all 4 weight matrices -> fp16 in one launch ---------------
// each matrix is 256*1024 floats = 65536 float4
__global__ void __launch_bounds__(256) convert_weights(
    const float4* __restrict__ Wq, const float4* __restrict__ Wk,
    const float4* __restrict__ Wv, const float4* __restrict__ Wo,
    uint2* __restrict__ Wh, uint2* __restrict__ Woh)
{
    const int i = blockIdx.x * 256 + threadIdx.x;   // 0..65535
    const int m = blockIdx.y;
    const float4* src = (m == 0) ? Wq : (m == 1) ? Wk : (m == 2) ? Wv : Wo;
    float4 v = src[i];
    uint2 r = make_uint2(pack_h(v.x, v.y), pack_h(v.z, v.w));
    if (m < 3) Wh[(size_t)m * 65536 + i] = r;
    else       Woh[i] = r;
}

// ============ split-fp16 HMMA GEMM: C = (Ah+Al) @ Bh^T ======================
// 128x128 CTA tile, BK=32, 3-stage cp.async pipeline, one barrier per chunk,
// 8 warps (2x4), warp 64x32, 2 CTAs/SM.
#define LDS_A   40
#define TILE_B  (128 * LDS_A * 2)   // 10240 B per fp16 tile
#define STAGE_B (3 * TILE_B)        // Ah Al Bh = 30720 B
#define NSTAGE  3
#define GEMM_SMEM (NSTAGE * STAGE_B)  // 92160 B

__global__ void __launch_bounds__(256, 2) hmma_gemm_fp16(
    const __half* __restrict__ Ah, const __half* __restrict__ Al, int lda,
    const __half* __restrict__ Bh, int ldb,
    float* __restrict__ C, int ldc, int K)
{
    extern __shared__ __align__(128) char smem[];
    const uint32_t sbase = smem_to_u32(smem);
    const int tid = threadIdx.x;
    const int w = tid >> 5, lane = tid & 31;
    const int m0 = blockIdx.y * 128;
    const int n0 = blockIdx.x * 128;

    // cp.async mapping: per tile, 256 threads x 2 rows of 16B
    const int row0 = tid >> 2, c16 = tid & 3;
    const int row1 = (tid + 256) >> 2;
    const uint32_t d0 = (uint32_t)row0 * (LDS_A * 2) + c16 * 16;
    const uint32_t d1 = (uint32_t)row1 * (LDS_A * 2) + c16 * 16;
    const size_t aoff0 = (size_t)(m0 + row0) * lda + c16 * 8;
    const size_t aoff1 = (size_t)(m0 + row1) * lda + c16 * 8;
    const size_t boff0 = (size_t)(n0 + row0) * ldb + c16 * 8;
    const size_t boff1 = (size_t)(n0 + row1) * ldb + c16 * 8;

#define ISSUE_STAGE(sb, koff) do { \
        cpa16((sb) + 0 * TILE_B + d0, Ah + aoff0 + (koff)); \
        cpa16((sb) + 0 * TILE_B + d1, Ah + aoff1 + (koff)); \
        cpa16((sb) + 1 * TILE_B + d0, Al + aoff0 + (koff)); \
        cpa16((sb) + 1 * TILE_B + d1, Al + aoff1 + (koff)); \
        cpa16((sb) + 2 * TILE_B + d0, Bh + boff0 + (koff)); \
        cpa16((sb) + 2 * TILE_B + d1, Bh + boff1 + (koff)); \
    } while (0)

    float acc[4][4][4];
#pragma unroll
    for (int mt = 0; mt < 4; mt++)
#pragma unroll
        for (int nt = 0; nt < 4; nt++)
#pragma unroll
            for (int r = 0; r < 4; r++) acc[mt][nt][r] = 0.f;

    const int wm = w >> 2, wn = w & 3;
    const int aRow = wm * 64 + (lane & 15);
    const int aCol = (lane >> 4) * 8;
    const int bRow = wn * 32 + (lane & 7) + ((lane >> 4) << 3);
    const int bCol = (lane & 8);

    const int NC = K / 32;   // NC >= 2 always here (8 or 32)

    // prologue: stages 0 and 1
    ISSUE_STAGE(sbase, 0);
    CPA_COMMIT();
    ISSUE_STAGE(sbase + STAGE_B, 32);
    CPA_COMMIT();

    int s = 0;
    for (int c = 0; c < NC; c++) {
        CPA_WAIT1();         // stage c resident (thread-local)
        __syncthreads();     // visibility + WAR fence for stage refill below
        if (c + 2 < NC) {
            int s2 = s + 2; if (s2 >= NSTAGE) s2 -= NSTAGE;
            ISSUE_STAGE(sbase + s2 * STAGE_B, (c + 2) * 32);
        }
        CPA_COMMIT();        // one group per iteration (possibly empty)

        const uint32_t st = sbase + s * STAGE_B;
        const uint32_t sAh = st, sAl = st + TILE_B, sB = st + 2 * TILE_B;
#pragma unroll
        for (int ks = 0; ks < 2; ks++) {
            const int kb = ks * 16;
            uint32_t bAddr = ((uint32_t)bRow * LDS_A + kb + bCol) * 2;
            uint32_t aAddr = ((uint32_t)aRow * LDS_A + kb + aCol) * 2;
            uint32_t bf[2][4], af[4][4];
#pragma unroll
            for (int nt2 = 0; nt2 < 2; nt2++)
                LDMX4(bf[nt2], sB + bAddr + nt2 * (16 * LDS_A * 2));
#pragma unroll
            for (int mt = 0; mt < 4; mt++)
                LDMX4(af[mt], sAh + aAddr + mt * (16 * LDS_A * 2));
#pragma unroll
            for (int mt = 0; mt < 4; mt++)
#pragma unroll
                for (int nt = 0; nt < 4; nt++)
                    MMA_FP16(acc[mt][nt], af[mt], &bf[nt >> 1][(nt & 1) * 2]);
#pragma unroll
            for (int mt = 0; mt < 4; mt++)
                LDMX4(af[mt], sAl + aAddr + mt * (16 * LDS_A * 2));
#pragma unroll
            for (int mt = 0; mt < 4; mt++)
#pragma unroll
                for (int nt = 0; nt < 4; nt++)
                    MMA_FP16(acc[mt][nt], af[mt], &bf[nt >> 1][(nt & 1) * 2]);
        }
        if (++s == NSTAGE) s = 0;
    }
#undef ISSUE_STAGE

    // epilogue
    const int gr = lane >> 2, gc = (lane & 3) * 2;
#pragma unroll
    for (int mt = 0; mt < 4; mt++) {
#pragma unroll
        for (int nt = 0; nt < 4; nt++) {
            float* dst = C + (size_t)(m0 + wm * 64 + mt * 16 + gr) * ldc
                           + n0 + wn * 32 + nt * 8 + gc;
            *(float2*)dst = make_float2(acc[mt][nt][0], acc[mt][nt][1]);
            *(float2*)(dst + (size_t)8 * ldc) =
                make_float2(acc[mt][nt][2], acc[mt][nt][3]);
        }
    }
}

// ---------------- fused pos_unit helper (per 4 elems, 16-lane row groups) ---
__device__ __forceinline__ float4 posunit4(float4 v) {
    float4 p;
    p.x = v.x > 0.f ? v.x + 1.f : __expf(v.x);
    p.y = v.y > 0.f ? v.y + 1.f : __expf(v.y);
    p.z = v.z > 0.f ? v.z + 1.f : __expf(v.z);
    p.w = v.w > 0.f ? v.w + 1.f : __expf(v.w);
    float s = p.x * p.x + p.y * p.y + p.z * p.z + p.w * p.w;
    s += __shfl_xor_sync(0xffffffffu, s, 8);
    s += __shfl_xor_sync(0xffffffffu, s, 4);
    s += __shfl_xor_sync(0xffffffffu, s, 2);
    s += __shfl_xor_sync(0xffffffffu, s, 1);
    float inv = 1.0f / (sqrtf(s) + EPSF);
    p.x *= inv; p.y *= inv; p.z *= inv; p.w *= inv;
    return p;
}

// ---------------- per-chunk sums (posunit fused on k) -----------------------
__global__ void __launch_bounds__(256) chunksum_kernel(
    const float* __restrict__ qkv, float* __restrict__ Sc, float* __restrict__ kcs)
{
    __shared__ float ks[64 * 64];
    __shared__ float vs[64 * 64];
    const int tid = threadIdx.x;
    const int c = blockIdx.x, bh = blockIdx.y;
    const int b = bh >> 2, h = bh & 3;
    const int nbase = b * TT + c * CHUNK;
    const int rowb = tid >> 4;
    const int dq = (tid & 15) * 4;
#pragma unroll
    for (int rep = 0; rep < 4; rep++) {
        int t = rowb + rep * 16;
        const float* src = qkv + (size_t)(nbase + t) * QKVW + h * 64 + dq;
        float4 k4 = posunit4(*(const float4*)(src + 256));
        *(float4*)&ks[t * 64 + dq] = k4;
        *(float4*)&vs[t * 64 + dq] = *(const float4*)(src + 512);
    }
    __syncthreads();
    const int tx = tid & 15, ty = tid >> 4;
    float acc[4][4];
#pragma unroll
    for (int i = 0; i < 4; i++)
#pragma unroll
        for (int j = 0; j < 4; j++) acc[i][j] = 0.f;
    for (int t = 0; t < 64; t++) {
        float4 vv = *(const float4*)&vs[t * 64 + ty * 4];
        float4 kv = *(const float4*)&ks[t * 64 + tx * 4];
        float vm[4] = {vv.x, vv.y, vv.z, vv.w};
        float km[4] = {kv.x, kv.y, kv.z, kv.w};
#pragma unroll
        for (int i = 0; i < 4; i++)
#pragma unroll
            for (int j = 0; j < 4; j++)
                acc[i][j] += vm[i] * km[j];
    }
    size_t base = ((size_t)bh * NCH + c) * 4096;
#pragma unroll
    for (int i = 0; i < 4; i++) {
        float4 o = make_float4(acc[i][0], acc[i][1], acc[i][2], acc[i][3]);
        *(float4*)(Sc + base + (size_t)(ty * 4 + i) * 64 + tx * 4) = o;
    }
    if (tid < 64) {
        float s = 0.f;
        for (int t = 0; t < 64; t++) s += ks[t * 64 + tid];
        kcs[((size_t)bh * NCH + c) * 64 + tid] = s;
    }
}

// ---------------- exclusive prefix over chunks + final-state outputs -------
__global__ void __launch_bounds__(256) prefix_kernel(
    const float* __restrict__ Sc, const float* __restrict__ kcs,
    float* __restrict__ S0, float* __restrict__ kc0,
    float* __restrict__ dout, int out_size)
{
    const int tid = threadIdx.x;
    const int bh = blockIdx.y;
    const int e = blockIdx.x * 256 + tid;   // 0..4095
    float acc = 0.f;
    for (int c = 0; c < NCH; c++) {
        size_t idx = ((size_t)bh * NCH + c) * 4096 + e;
        S0[idx] = acc;
        acc += Sc[idx];
    }
    int kvoff = YSZ + bh * 4096 + e;
    if (kvoff < out_size) dout[kvoff] = acc;    // kv_f [B,H,j,d]
    if (blockIdx.x == 0 && tid < 64) {
        float a2 = 0.f;
        for (int c = 0; c < NCH; c++) {
            size_t idx = ((size_t)bh * NCH + c) * 64 + tid;
            kc0[idx] = a2;
            a2 += kcs[idx];
        }
        int kcoff = YSZ + KVSZ + bh * 64 + tid;
        if (kcoff < out_size) dout[kcoff] = a2; // kc_f [B,H,d]
    }
}

// ---------------- intra-chunk attention (posunit fused; y -> split fp16) ---
#define SMEM_INTRA (( (64*68)*3 + 64*64 + 64*68 + 64 + 64 ) * 4)
__global__ void __launch_bounds__(256) intra_kernel(
    const float* __restrict__ qkv, const float* __restrict__ S0g,
    const float* __restrict__ kc0g,
    __half* __restrict__ yh, __half* __restrict__ yl)
{
    extern __shared__ float smf[];
    float* Qt  = smf;              // [dd][t]  64x68 (transposed)
    float* Kt  = Qt + 64 * 68;     // [dd][t]  64x68
    float* St  = Kt + 64 * 68;     // [dd][j]  64x68 (S0 transposed)
    float* Vs  = St + 64 * 68;     // [t][j]   64x64
    float* Am  = Vs + 64 * 64;     // [r][c]   64x68
    float* kc0 = Am + 64 * 68;     // 64
    float* dens = kc0 + 64;        // 64

    const int tid = threadIdx.x;
    const int c = blockIdx.x, bh = blockIdx.y;
    const int b = bh >> 2, h = bh & 3;
    const int nbase = b * TT + c * CHUNK;
    const int rowb = tid >> 4;
    const int dq = (tid & 15) * 4;

    size_t s0base = ((size_t)bh * NCH + c) * 4096;
#pragma unroll
    for (int rep = 0; rep < 4; rep++) {
        int t = rowb + rep * 16;
        const float* src = qkv + (size_t)(nbase + t) * QKVW + h * 64 + dq;
        float4 q4 = posunit4(*(const float4*)(src));
        float4 k4 = posunit4(*(const float4*)(src + 256));
        float4 v4 = *(const float4*)(src + 512);
        Qt[(dq + 0) * 68 + t] = q4.x; Qt[(dq + 1) * 68 + t] = q4.y;
        Qt[(dq + 2) * 68 + t] = q4.z; Qt[(dq + 3) * 68 + t] = q4.w;
        Kt[(dq + 0) * 68 + t] = k4.x; Kt[(dq + 1) * 68 + t] = k4.y;
        Kt[(dq + 2) * 68 + t] = k4.z; Kt[(dq + 3) * 68 + t] = k4.w;
        *(float4*)&Vs[t * 64 + dq] = v4;
        float4 s4 = *(const float4*)(S0g + s0base + (size_t)t * 64 + dq);
        St[(dq + 0) * 68 + t] = s4.x; St[(dq + 1) * 68 + t] = s4.y;
        St[(dq + 2) * 68 + t] = s4.z; St[(dq + 3) * 68 + t] = s4.w;
    }
    if (tid < 64) kc0[tid] = kc0g[((size_t)bh * NCH + c) * 64 + tid];
    __syncthreads();

    const int tx = tid & 15, ty = tid >> 4;
    float a[4][4];
#pragma unroll
    for (int i = 0; i < 4; i++)
#pragma unroll
        for (int j = 0; j < 4; j++) a[i][j] = 0.f;
    for (int dd = 0; dd < 64; dd++) {
        float4 qv = *(const float4*)&Qt[dd * 68 + ty * 4];
        float4 kv = *(const float4*)&Kt[dd * 68 + tx * 4];
        float qm[4] = {qv.x, qv.y, qv.z, qv.w};
        float km[4] = {kv.x, kv.y, kv.z, kv.w};
#pragma unroll
        for (int i = 0; i < 4; i++)
#pragma unroll
            for (int j = 0; j < 4; j++)
                a[i][j] += qm[i] * km[j];
    }
#pragma unroll
    for (int i = 0; i < 4; i++) {
        int r = ty * 4 + i;
#pragma unroll
        for (int j = 0; j < 4; j++) {
            int cc = tx * 4 + j;
            Am[r * 68 + cc] = (cc <= r) ? a[i][j] : 0.f;
        }
    }
    __syncthreads();
    if (tid < 64) {
        int r = tid;
        float s = EPSF;
        for (int cc = 0; cc <= r; cc++) s += Am[r * 68 + cc];
        for (int dd = 0; dd < 64; dd++) s += Qt[dd * 68 + r] * kc0[dd];
        dens[r] = s;
    }
    __syncthreads();
    float acc[4][4];
#pragma unroll
    for (int i = 0; i < 4; i++)
#pragma unroll
        for (int j = 0; j < 4; j++) acc[i][j] = 0.f;
    for (int cc = 0; cc < 64; cc++) {
        float4 vv = *(const float4*)&Vs[cc * 64 + tx * 4];
        float vm[4] = {vv.x, vv.y, vv.z, vv.w};
        float amv[4] = {Am[(ty * 4 + 0) * 68 + cc], Am[(ty * 4 + 1) * 68 + cc],
                        Am[(ty * 4 + 2) * 68 + cc], Am[(ty * 4 + 3) * 68 + cc]};
#pragma unroll
        for (int i = 0; i < 4; i++)
#pragma unroll
            for (int j = 0; j < 4; j++)
                acc[i][j] += amv[i] * vm[j];
    }
    for (int dd = 0; dd < 64; dd++) {
        float4 qv = *(const float4*)&Qt[dd * 68 + ty * 4];
        float4 sv = *(const float4*)&St[dd * 68 + tx * 4];
        float qm[4] = {qv.x, qv.y, qv.z, qv.w};
        float smv[4] = {sv.x, sv.y, sv.z, sv.w};
#pragma unroll
        for (int i = 0; i < 4; i++)
#pragma unroll
            for (int j = 0; j < 4; j++)
                acc[i][j] += qm[i] * smv[j];
    }
#pragma unroll
    for (int i = 0; i < 4; i++) {
        int r = ty * 4 + i;
        float inv = 1.0f / dens[r];
        float4 o = make_float4(acc[i][0] * inv, acc[i][1] * inv,
                               acc[i][2] * inv, acc[i][3] * inv);
        uint2 hbits, lbits;
        split4h(o, hbits, lbits);
        size_t off = (size_t)(nbase + r) * 256 + h * 64 + tx * 4;
        *(uint2*)(yh + off) = hbits;
        *(uint2*)(yl + off) = lbits;
    }
}

// ---------------------------------------------------------------------------
extern "C" void kernel_launch(void* const* d_in, const int* in_sizes, int n_in,
                              void* d_out, int out_size)
{
    const float* x  = (const float*)d_in[0];
    const float* Wq = (const float*)d_in[1];
    const float* Wk = (const float*)d_in[2];
    const float* Wv = (const float*)d_in[3];
    const float* Wo = (const float*)d_in[4];
    float* out = (float*)d_out;

    float *qkv, *Sc, *S0, *kc, *kc0;
    __half *xh, *xl, *Wh, *Woh, *yh, *yl;
    cudaGetSymbolAddress((void**)&qkv, g_qkv);
    cudaGetSymbolAddress((void**)&Sc,  g_Sc);
    cudaGetSymbolAddress((void**)&S0,  g_S0);
    cudaGetSymbolAddress((void**)&kc,  g_kc);
    cudaGetSymbolAddress((void**)&kc0, g_kc0);
    cudaGetSymbolAddress((void**)&xh,  g_xh);
    cudaGetSymbolAddress((void**)&xl,  g_xl);
    cudaGetSymbolAddress((void**)&Wh,  g_Wh);
    cudaGetSymbolAddress((void**)&Woh, g_Woh);
    cudaGetSymbolAddress((void**)&yh,  g_yh);
    cudaGetSymbolAddress((void**)&yl,  g_yl);

    cudaFuncSetAttribute(intra_kernel,
                         cudaFuncAttributeMaxDynamicSharedMemorySize, SMEM_INTRA);
    cudaFuncSetAttribute(hmma_gemm_fp16,
                         cudaFuncAttributeMaxDynamicSharedMemorySize, GEMM_SMEM);

    // operand preparation: x -> exact fp16 pair; weights -> single fp16
    convert_split<<<(NTOK * DDIM / 4 + 255) / 256, 256>>>(
        (const float4*)x, (uint2*)xh, (uint2*)xl, NTOK * DDIM / 4);
    convert_weights<<<dim3(256, 4), 256>>>(
        (const float4*)Wq, (const float4*)Wk, (const float4*)Wv,
        (const float4*)Wo, (uint2*)Wh, (uint2*)Woh);

    // QKV projection: qkv[t][0:768] = x @ [Wq;Wk;Wv]^T
    hmma_gemm_fp16<<<dim3(6, NTOK / 128), 256, GEMM_SMEM>>>(
        xh, xl, DDIM, Wh, DDIM, qkv, QKVW, DDIM);

    // chunked linear-attention scan (posunit fused into consumers)
    chunksum_kernel<<<dim3(NCH, NBH), 256>>>(qkv, Sc, kc);
    prefix_kernel<<<dim3(16, NBH), 256>>>(Sc, kc, S0, kc0, out, out_size);
    intra_kernel<<<dim3(NCH, NBH), 256, SMEM_INTRA>>>(qkv, S0, kc0, yh, yl);

    // output projection: out = y @ Wo^T
    hmma_gemm_fp16<<<dim3(8, NTOK / 128), 256, GEMM_SMEM>>>(
        yh, yl, 256, Woh, 256, out, DDIM, 256);
}

// round 7
// speedup vs baseline: 3.5167x; 1.1048x over previous
#include <cuda_runtime.h>
#include <cuda_fp16.h>
#include <cstdint>

#define EPSF 1e-6f

// Problem constants (B=4, T=4096, D=1024, H=4, d=64)
#define BB    4
#define TT    4096
#define DDIM  1024
#define HH    4
#define HD    64
#define NTOK  (BB*TT)        // 16384
#define QKVW  768
#define CHUNK 64
#define NCH   (TT/CHUNK)     // 64
#define NBH   (BB*HH)        // 16
#define YSZ   (16777216)     // NTOK*DDIM
#define KVSZ  (65536)        // NBH*64*64

// ---------------- scratch (device globals; no allocations allowed) ----------
__device__ __align__(128) float g_qkv[(size_t)NTOK * QKVW];          // 48 MB
__device__ __align__(128) float g_Sc [(size_t)NBH * NCH * 4096];     // 16 MB
__device__ __align__(128) float g_S0 [(size_t)NBH * NCH * 4096];     // 16 MB
__device__ __align__(128) float g_kc [(size_t)NBH * NCH * 64];
__device__ __align__(128) float g_kc0[(size_t)NBH * NCH * 64];
// split-fp16 operand copies
__device__ __align__(128) __half g_xh[(size_t)NTOK * DDIM];          // 32 MB
__device__ __align__(128) __half g_xl[(size_t)NTOK * DDIM];          // 32 MB
__device__ __align__(128) __half g_Wh[(size_t)QKVW * DDIM];          // 1.5 MB
__device__ __align__(128) __half g_Woh[(size_t)DDIM * 256];
__device__ __align__(128) __half g_yh[(size_t)NTOK * 256];           // 8 MB
__device__ __align__(128) __half g_yl[(size_t)NTOK * 256];           // 8 MB

// ======================= PTX helpers (arch-neutral) =========================
__device__ __forceinline__ uint32_t smem_to_u32(const void* p) {
    uint32_t a;
    asm("{ .reg .u64 t; cvta.to.shared.u64 t, %1; cvt.u32.u64 %0, t; }"
        : "=r"(a) : "l"(p));
    return a;
}
#define LDMX4(R, addr) \
    asm volatile("ldmatrix.sync.aligned.m8n8.x4.shared.b16 {%0,%1,%2,%3}, [%4];" \
        : "=r"((R)[0]), "=r"((R)[1]), "=r"((R)[2]), "=r"((R)[3]) : "r"(addr))
#define MMA_FP16(D, A, B) \
    asm volatile("mma.sync.aligned.m16n8k16.row.col.f32.f16.f16.f32 " \
        "{%0,%1,%2,%3},{%4,%5,%6,%7},{%8,%9},{%0,%1,%2,%3};" \
        : "+f"((D)[0]), "+f"((D)[1]), "+f"((D)[2]), "+f"((D)[3]) \
        : "r"((A)[0]), "r"((A)[1]), "r"((A)[2]), "r"((A)[3]), \
          "r"((B)[0]), "r"((B)[1]))
__device__ __forceinline__ void cpa16(uint32_t dst, const void* src) {
    asm volatile("cp.async.cg.shared.global [%0], [%1], 16;"
                 :: "r"(dst), "l"(src) : "memory");
}
#define CPA_COMMIT() asm volatile("cp.async.commit_group;" ::: "memory")
#define CPA_WAIT1()  asm volatile("cp.async.wait_group 1;"  ::: "memory")

__device__ __forceinline__ uint32_t pack_h(float a, float b) {
    __half2 t;
    t.x = __float2half_rn(a);
    t.y = __float2half_rn(b);
    return *(uint32_t*)&t;
}
// exact fp16 (hi, lo) split of a float pair
__device__ __forceinline__ void split2h(float a, float b, uint32_t& h, uint32_t& l) {
    float ha = __half2float(__float2half_rn(a));
    float hb = __half2float(__float2half_rn(b));
    h = pack_h(a, b);
    l = pack_h(a - ha, b - hb);
}
// exact fp16 (hi, lo) split of a float4
__device__ __forceinline__ void split4h(float4 v, uint2& h, uint2& l) {
    split2h(v.x, v.y, h.x, l.x);
    split2h(v.z, v.w, h.y, l.y);
}

// ---------------- fp32 -> (hi, lo) fp16 split (x) --------------------------
__global__ void __launch_bounds__(256) convert_split(
    const float4* __restrict__ src, uint2* __restrict__ dh,
    uint2* __restrict__ dl, int n4)
{
    int i = blockIdx.x * 256 + threadIdx.x;
    if (i < n4) {
        uint2 h, l;
        split4h(src[i], h, l);
        dh[i] = h;
        dl[i] = l;
    }
}
// ---------------- all 4 weight matrices -> fp16 in one launch ---------------
__global__ void __launch_bounds__(256) convert_weights(
    const float4* __restrict__ Wq, const float4* __restrict__ Wk,
    const float4* __restrict__ Wv, const float4* __restrict__ Wo,
    uint2* __restrict__ Wh, uint2* __restrict__ Woh)
{
    const int i = blockIdx.x * 256 + threadIdx.x;   // 0..65535
    const int m = blockIdx.y;
    const float4* src = (m == 0) ? Wq : (m == 1) ? Wk : (m == 2) ? Wv : Wo;
    float4 v = src[i];
    uint2 r = make_uint2(pack_h(v.x, v.y), pack_h(v.z, v.w));
    if (m < 3) Wh[(size_t)m * 65536 + i] = r;
    else       Woh[i] = r;
}

// ============ split-fp16 HMMA GEMM: C = (Ah+Al) @ Bh^T ======================
#define LDS_A   40
#define TILE_B  (128 * LDS_A * 2)
#define STAGE_B (3 * TILE_B)
#define NSTAGE  3
#define GEMM_SMEM (NSTAGE * STAGE_B)  // 92160 B

__global__ void __launch_bounds__(256, 2) hmma_gemm_fp16(
    const __half* __restrict__ Ah, const __half* __restrict__ Al, int lda,
    const __half* __restrict__ Bh, int ldb,
    float* __restrict__ C, int ldc, int K)
{
    extern __shared__ __align__(128) char smem[];
    const uint32_t sbase = smem_to_u32(smem);
    const int tid = threadIdx.x;
    const int w = tid >> 5, lane = tid & 31;
    const int m0 = blockIdx.y * 128;
    const int n0 = blockIdx.x * 128;

    const int row0 = tid >> 2, c16 = tid & 3;
    const int row1 = (tid + 256) >> 2;
    const uint32_t d0 = (uint32_t)row0 * (LDS_A * 2) + c16 * 16;
    const uint32_t d1 = (uint32_t)row1 * (LDS_A * 2) + c16 * 16;
    const size_t aoff0 = (size_t)(m0 + row0) * lda + c16 * 8;
    const size_t aoff1 = (size_t)(m0 + row1) * lda + c16 * 8;
    const size_t boff0 = (size_t)(n0 + row0) * ldb + c16 * 8;
    const size_t boff1 = (size_t)(n0 + row1) * ldb + c16 * 8;

#define ISSUE_STAGE(sb, koff) do { \
        cpa16((sb) + 0 * TILE_B + d0, Ah + aoff0 + (koff)); \
        cpa16((sb) + 0 * TILE_B + d1, Ah + aoff1 + (koff)); \
        cpa16((sb) + 1 * TILE_B + d0, Al + aoff0 + (koff)); \
        cpa16((sb) + 1 * TILE_B + d1, Al + aoff1 + (koff)); \
        cpa16((sb) + 2 * TILE_B + d0, Bh + boff0 + (koff)); \
        cpa16((sb) + 2 * TILE_B + d1, Bh + boff1 + (koff)); \
    } while (0)

    float acc[4][4][4];
#pragma unroll
    for (int mt = 0; mt < 4; mt++)
#pragma unroll
        for (int nt = 0; nt < 4; nt++)
#pragma unroll
            for (int r = 0; r < 4; r++) acc[mt][nt][r] = 0.f;

    const int wm = w >> 2, wn = w & 3;
    const int aRow = wm * 64 + (lane & 15);
    const int aCol = (lane >> 4) * 8;
    const int bRow = wn * 32 + (lane & 7) + ((lane >> 4) << 3);
    const int bCol = (lane & 8);

    const int NC = K / 32;

    ISSUE_STAGE(sbase, 0);
    CPA_COMMIT();
    ISSUE_STAGE(sbase + STAGE_B, 32);
    CPA_COMMIT();

    int s = 0;
    for (int c = 0; c < NC; c++) {
        CPA_WAIT1();
        __syncthreads();
        if (c + 2 < NC) {
            int s2 = s + 2; if (s2 >= NSTAGE) s2 -= NSTAGE;
            ISSUE_STAGE(sbase + s2 * STAGE_B, (c + 2) * 32);
        }
        CPA_COMMIT();

        const uint32_t st = sbase + s * STAGE_B;
        const uint32_t sAh = st, sAl = st + TILE_B, sB = st + 2 * TILE_B;
#pragma unroll
        for (int ks = 0; ks < 2; ks++) {
            const int kb = ks * 16;
            uint32_t bAddr = ((uint32_t)bRow * LDS_A + kb + bCol) * 2;
            uint32_t aAddr = ((uint32_t)aRow * LDS_A + kb + aCol) * 2;
            uint32_t bf[2][4], af[4][4];
#pragma unroll
            for (int nt2 = 0; nt2 < 2; nt2++)
                LDMX4(bf[nt2], sB + bAddr + nt2 * (16 * LDS_A * 2));
#pragma unroll
            for (int mt = 0; mt < 4; mt++)
                LDMX4(af[mt], sAh + aAddr + mt * (16 * LDS_A * 2));
#pragma unroll
            for (int mt = 0; mt < 4; mt++)
#pragma unroll
                for (int nt = 0; nt < 4; nt++)
                    MMA_FP16(acc[mt][nt], af[mt], &bf[nt >> 1][(nt & 1) * 2]);
#pragma unroll
            for (int mt = 0; mt < 4; mt++)
                LDMX4(af[mt], sAl + aAddr + mt * (16 * LDS_A * 2));
#pragma unroll
            for (int mt = 0; mt < 4; mt++)
#pragma unroll
                for (int nt = 0; nt < 4; nt++)
                    MMA_FP16(acc[mt][nt], af[mt], &bf[nt >> 1][(nt & 1) * 2]);
        }
        if (++s == NSTAGE) s = 0;
    }
#undef ISSUE_STAGE

    const int gr = lane >> 2, gc = (lane & 3) * 2;
#pragma unroll
    for (int mt = 0; mt < 4; mt++) {
#pragma unroll
        for (int nt = 0; nt < 4; nt++) {
            float* dst = C + (size_t)(m0 + wm * 64 + mt * 16 + gr) * ldc
                           + n0 + wn * 32 + nt * 8 + gc;
            *(float2*)dst = make_float2(acc[mt][nt][0], acc[mt][nt][1]);
            *(float2*)(dst + (size_t)8 * ldc) =
                make_float2(acc[mt][nt][2], acc[mt][nt][3]);
        }
    }
}

// ---------------- fused pos_unit helper (per 4 elems, 16-lane row groups) ---
__device__ __forceinline__ float4 posunit4(float4 v) {
    float4 p;
    p.x = v.x > 0.f ? v.x + 1.f : __expf(v.x);
    p.y = v.y > 0.f ? v.y + 1.f : __expf(v.y);
    p.z = v.z > 0.f ? v.z + 1.f : __expf(v.z);
    p.w = v.w > 0.f ? v.w + 1.f : __expf(v.w);
    float s = p.x * p.x + p.y * p.y + p.z * p.z + p.w * p.w;
    s += __shfl_xor_sync(0xffffffffu, s, 8);
    s += __shfl_xor_sync(0xffffffffu, s, 4);
    s += __shfl_xor_sync(0xffffffffu, s, 2);
    s += __shfl_xor_sync(0xffffffffu, s, 1);
    float inv = 1.0f / (sqrtf(s) + EPSF);
    p.x *= inv; p.y *= inv; p.z *= inv; p.w *= inv;
    return p;
}

// ---------------- per-chunk sums (posunit fused on k) -----------------------
__global__ void __launch_bounds__(256) chunksum_kernel(
    const float* __restrict__ qkv, float* __restrict__ Sc, float* __restrict__ kcs)
{
    __shared__ float ks[64 * 64];
    __shared__ float vs[64 * 64];
    const int tid = threadIdx.x;
    const int c = blockIdx.x, bh = blockIdx.y;
    const int b = bh >> 2, h = bh & 3;
    const int nbase = b * TT + c * CHUNK;
    const int rowb = tid >> 4;
    const int dq = (tid & 15) * 4;
#pragma unroll
    for (int rep = 0; rep < 4; rep++) {
        int t = rowb + rep * 16;
        const float* src = qkv + (size_t)(nbase + t) * QKVW + h * 64 + dq;
        float4 k4 = posunit4(*(const float4*)(src + 256));
        *(float4*)&ks[t * 64 + dq] = k4;
        *(float4*)&vs[t * 64 + dq] = *(const float4*)(src + 512);
    }
    __syncthreads();
    const int tx = tid & 15, ty = tid >> 4;
    float acc[4][4];
#pragma unroll
    for (int i = 0; i < 4; i++)
#pragma unroll
        for (int j = 0; j < 4; j++) acc[i][j] = 0.f;
    for (int t = 0; t < 64; t++) {
        float4 vv = *(const float4*)&vs[t * 64 + ty * 4];
        float4 kv = *(const float4*)&ks[t * 64 + tx * 4];
        float vm[4] = {vv.x, vv.y, vv.z, vv.w};
        float km[4] = {kv.x, kv.y, kv.z, kv.w};
#pragma unroll
        for (int i = 0; i < 4; i++)
#pragma unroll
            for (int j = 0; j < 4; j++)
                acc[i][j] += vm[i] * km[j];
    }
    size_t base = ((size_t)bh * NCH + c) * 4096;
#pragma unroll
    for (int i = 0; i < 4; i++) {
        float4 o = make_float4(acc[i][0], acc[i][1], acc[i][2], acc[i][3]);
        *(float4*)(Sc + base + (size_t)(ty * 4 + i) * 64 + tx * 4) = o;
    }
    if (tid < 64) {
        float s = 0.f;
        for (int t = 0; t < 64; t++) s += ks[t * 64 + tid];
        kcs[((size_t)bh * NCH + c) * 64 + tid] = s;
    }
}

// ---------------- exclusive prefix over chunks + final-state outputs -------
__global__ void __launch_bounds__(256) prefix_kernel(
    const float* __restrict__ Sc, const float* __restrict__ kcs,
    float* __restrict__ S0, float* __restrict__ kc0,
    float* __restrict__ dout, int out_size)
{
    const int tid = threadIdx.x;
    const int bh = blockIdx.y;
    const int e = blockIdx.x * 256 + tid;   // 0..4095
    float acc = 0.f;
    for (int c = 0; c < NCH; c++) {
        size_t idx = ((size_t)bh * NCH + c) * 4096 + e;
        S0[idx] = acc;
        acc += Sc[idx];
    }
    int kvoff = YSZ + bh * 4096 + e;
    if (kvoff < out_size) dout[kvoff] = acc;    // kv_f [B,H,j,d]
    if (blockIdx.x == 0 && tid < 64) {
        float a2 = 0.f;
        for (int c = 0; c < NCH; c++) {
            size_t idx = ((size_t)bh * NCH + c) * 64 + tid;
            kc0[idx] = a2;
            a2 += kcs[idx];
        }
        int kcoff = YSZ + KVSZ + bh * 64 + tid;
        if (kcoff < out_size) dout[kcoff] = a2; // kc_f [B,H,d]
    }
}

// =========== intra-chunk attention via split-fp16 HMMA ======================
// num = tril(QK^T)V + Q@S0 ; den = eps + rowsum(tril(QK^T)) + q.kc0
// All operands split into exact fp16 (hi,lo) pairs; each 64x64x64 matmul is
// 3 MMA terms (hh + hl + lh), fp32 accumulation. Error ~2^-22 (negligible).
#define IST 72                             // fp16 row stride (144B = 9*16B)
#define IBUF (64 * IST)                    // halves per buffer
// buffers: Qh Ql Ah(K->A) Al Vth Vtl S0h S0l  + dens[64] kc0[64] fp32
#define INTRA_SMEM (8 * IBUF * 2 + 128 * 4)

// one 64x64x64 MMA-accumulate: acc += A(sA) @ B(sB)^T, warp tile 16x32
__device__ __forceinline__ void mm64(
    uint32_t sA, uint32_t sB, int wm, int wn, int lane, float acc[4][4])
{
    const uint32_t aBase = sA +
        (((uint32_t)(wm * 16 + (lane & 15)) * IST + ((lane >> 4) * 8)) * 2);
    const uint32_t bBase = sB +
        (((uint32_t)(wn * 32 + (lane & 7) + ((lane >> 4) << 3)) * IST + (lane & 8)) * 2);
#pragma unroll
    for (int ks = 0; ks < 4; ks++) {
        const uint32_t ko = ks * 32;   // 16 halves
        uint32_t af[4], bf0[4], bf1[4];
        LDMX4(af, aBase + ko);
        LDMX4(bf0, bBase + ko);
        LDMX4(bf1, bBase + ko + 16 * IST * 2);
        MMA_FP16(acc[0], af, &bf0[0]);
        MMA_FP16(acc[1], af, &bf0[2]);
        MMA_FP16(acc[2], af, &bf1[0]);
        MMA_FP16(acc[3], af, &bf1[2]);
    }
}

__global__ void __launch_bounds__(256) intra_kernel(
    const float* __restrict__ qkv, const float* __restrict__ S0g,
    const float* __restrict__ kc0g,
    __half* __restrict__ yh, __half* __restrict__ yl)
{
    extern __shared__ __align__(128) char ism[];
    __half* bufs = (__half*)ism;
    __half* Qh  = bufs;             __half* Ql  = bufs + 1 * IBUF;
    __half* Ahb = bufs + 2 * IBUF;  __half* Alb = bufs + 3 * IBUF;  // K then A
    __half* Vth = bufs + 4 * IBUF;  __half* Vtl = bufs + 5 * IBUF;
    __half* S0h = bufs + 6 * IBUF;  __half* S0l = bufs + 7 * IBUF;
    float* dens = (float*)(bufs + 8 * IBUF);
    float* kc0s = dens + 64;

    const uint32_t sQh = smem_to_u32(Qh),  sQl = smem_to_u32(Ql);
    const uint32_t sAh = smem_to_u32(Ahb), sAl = smem_to_u32(Alb);
    const uint32_t sVh = smem_to_u32(Vth), sVl = smem_to_u32(Vtl);
    const uint32_t sSh = smem_to_u32(S0h), sSl = smem_to_u32(S0l);

    const int tid = threadIdx.x;
    const int w = tid >> 5, lane = tid & 31;
    const int c = blockIdx.x, bh = blockIdx.y;
    const int b = bh >> 2, h = bh & 3;
    const int nbase = b * TT + c * CHUNK;
    const int rowb = tid >> 4;
    const int dq = (tid & 15) * 4;
    const size_t s0base = ((size_t)bh * NCH + c) * 4096;

    // ---- load + posunit + split to fp16 smem ----
#pragma unroll
    for (int rep = 0; rep < 4; rep++) {
        int t = rowb + rep * 16;
        const float* src = qkv + (size_t)(nbase + t) * QKVW + h * 64 + dq;
        float4 q4 = posunit4(*(const float4*)(src));
        float4 k4 = posunit4(*(const float4*)(src + 256));
        float4 v4 = *(const float4*)(src + 512);
        float4 s4 = *(const float4*)(S0g + s0base + (size_t)t * 64 + dq);
        uint2 hh, ll;
        split4h(q4, hh, ll);
        *(uint2*)&Qh[t * IST + dq] = hh;  *(uint2*)&Ql[t * IST + dq] = ll;
        split4h(k4, hh, ll);
        *(uint2*)&Ahb[t * IST + dq] = hh; *(uint2*)&Alb[t * IST + dq] = ll;
        split4h(s4, hh, ll);
        *(uint2*)&S0h[t * IST + dq] = hh; *(uint2*)&S0l[t * IST + dq] = ll;
        // V transposed: Vt[j][t]
        float vv[4] = {v4.x, v4.y, v4.z, v4.w};
#pragma unroll
        for (int i = 0; i < 4; i++) {
            __half vh = __float2half_rn(vv[i]);
            Vth[(dq + i) * IST + t] = vh;
            Vtl[(dq + i) * IST + t] = __float2half_rn(vv[i] - __half2float(vh));
        }
    }
    if (tid < 64) {
        dens[tid] = EPSF;
        kc0s[tid] = kc0g[((size_t)bh * NCH + c) * 64 + tid];
    }
    __syncthreads();

    const int wm = w >> 1, wn = w & 1;      // 4x2 warp grid, tile 16x32
    const int gr = lane >> 2, gc = (lane & 3) * 2;
    const int r0 = wm * 16 + gr, r1 = r0 + 8;

    // ---- A = Q K^T (3 split terms) ----
    float a4[4][4];
#pragma unroll
    for (int nt = 0; nt < 4; nt++)
#pragma unroll
        for (int r = 0; r < 4; r++) a4[nt][r] = 0.f;
    mm64(sQh, sAh, wm, wn, lane, a4);
    mm64(sQh, sAl, wm, wn, lane, a4);
    mm64(sQl, sAh, wm, wn, lane, a4);
    __syncthreads();   // everyone done reading K before A overwrites it

    // ---- mask tril, row-sums, split-store A over K buffers ----
    float s0 = 0.f, s1 = 0.f;
#pragma unroll
    for (int nt = 0; nt < 4; nt++) {
        int c0 = wn * 32 + nt * 8 + gc;
        float m00 = (c0     <= r0) ? a4[nt][0] : 0.f;
        float m01 = (c0 + 1 <= r0) ? a4[nt][1] : 0.f;
        float m10 = (c0     <= r1) ? a4[nt][2] : 0.f;
        float m11 = (c0 + 1 <= r1) ? a4[nt][3] : 0.f;
        s0 += m00 + m01;
        s1 += m10 + m11;
        uint32_t hh, ll;
        split2h(m00, m01, hh, ll);
        *(uint32_t*)&Ahb[r0 * IST + c0] = hh;
        *(uint32_t*)&Alb[r0 * IST + c0] = ll;
        split2h(m10, m11, hh, ll);
        *(uint32_t*)&Ahb[r1 * IST + c0] = hh;
        *(uint32_t*)&Alb[r1 * IST + c0] = ll;
    }
    s0 += __shfl_xor_sync(0xffffffffu, s0, 1);
    s0 += __shfl_xor_sync(0xffffffffu, s0, 2);
    s1 += __shfl_xor_sync(0xffffffffu, s1, 1);
    s1 += __shfl_xor_sync(0xffffffffu, s1, 2);
    if ((lane & 3) == 0) {
        atomicAdd(&dens[r0], s0);
        atomicAdd(&dens[r1], s1);
    }
    // den += q . kc0 (exact q = Qh + Ql)
    if (tid < 64) {
        float qd = 0.f;
        for (int dd = 0; dd < 64; dd++)
            qd += (__half2float(Qh[tid * IST + dd]) +
                   __half2float(Ql[tid * IST + dd])) * kc0s[dd];
        atomicAdd(&dens[tid], qd);
    }
    __syncthreads();

    // ---- num = A V + Q S0 (3 + 3 split terms) ----
    float y4[4][4];
#pragma unroll
    for (int nt = 0; nt < 4; nt++)
#pragma unroll
        for (int r = 0; r < 4; r++) y4[nt][r] = 0.f;
    mm64(sAh, sVh, wm, wn, lane, y4);
    mm64(sAh, sVl, wm, wn, lane, y4);
    mm64(sAl, sVh, wm, wn, lane, y4);
    mm64(sQh, sSh, wm, wn, lane, y4);
    mm64(sQh, sSl, wm, wn, lane, y4);
    mm64(sQl, sSh, wm, wn, lane, y4);

    const float inv0 = 1.0f / dens[r0];
    const float inv1 = 1.0f / dens[r1];
#pragma unroll
    for (int nt = 0; nt < 4; nt++) {
        int c0 = wn * 32 + nt * 8 + gc;
        uint32_t hh, ll;
        size_t off0 = (size_t)(nbase + r0) * 256 + h * 64 + c0;
        split2h(y4[nt][0] * inv0, y4[nt][1] * inv0, hh, ll);
        *(uint32_t*)&yh[off0] = hh;
        *(uint32_t*)&yl[off0] = ll;
        size_t off1 = (size_t)(nbase + r1) * 256 + h * 64 + c0;
        split2h(y4[nt][2] * inv1, y4[nt][3] * inv1, hh, ll);
        *(uint32_t*)&yh[off1] = hh;
        *(uint32_t*)&yl[off1] = ll;
    }
}

// ---------------------------------------------------------------------------
extern "C" void kernel_launch(void* const* d_in, const int* in_sizes, int n_in,
                              void* d_out, int out_size)
{
    const float* x  = (const float*)d_in[0];
    const float* Wq = (const float*)d_in[1];
    const float* Wk = (const float*)d_in[2];
    const float* Wv = (const float*)d_in[3];
    const float* Wo = (const float*)d_in[4];
    float* out = (float*)d_out;

    float *qkv, *Sc, *S0, *kc, *kc0;
    __half *xh, *xl, *Wh, *Woh, *yh, *yl;
    cudaGetSymbolAddress((void**)&qkv, g_qkv);
    cudaGetSymbolAddress((void**)&Sc,  g_Sc);
    cudaGetSymbolAddress((void**)&S0,  g_S0);
    cudaGetSymbolAddress((void**)&kc,  g_kc);
    cudaGetSymbolAddress((void**)&kc0, g_kc0);
    cudaGetSymbolAddress((void**)&xh,  g_xh);
    cudaGetSymbolAddress((void**)&xl,  g_xl);
    cudaGetSymbolAddress((void**)&Wh,  g_Wh);
    cudaGetSymbolAddress((void**)&Woh, g_Woh);
    cudaGetSymbolAddress((void**)&yh,  g_yh);
    cudaGetSymbolAddress((void**)&yl,  g_yl);

    cudaFuncSetAttribute(intra_kernel,
                         cudaFuncAttributeMaxDynamicSharedMemorySize, INTRA_SMEM);
    cudaFuncSetAttribute(hmma_gemm_fp16,
                         cudaFuncAttributeMaxDynamicSharedMemorySize, GEMM_SMEM);

    // operand preparation: x -> exact fp16 pair; weights -> single fp16
    convert_split<<<(NTOK * DDIM / 4 + 255) / 256, 256>>>(
        (const float4*)x, (uint2*)xh, (uint2*)xl, NTOK * DDIM / 4);
    convert_weights<<<dim3(256, 4), 256>>>(
        (const float4*)Wq, (const float4*)Wk, (const float4*)Wv,
        (const float4*)Wo, (uint2*)Wh, (uint2*)Woh);

    // QKV projection: qkv[t][0:768] = x @ [Wq;Wk;Wv]^T
    hmma_gemm_fp16<<<dim3(6, NTOK / 128), 256, GEMM_SMEM>>>(
        xh, xl, DDIM, Wh, DDIM, qkv, QKVW, DDIM);

    // chunked linear-attention scan (posunit fused into consumers)
    chunksum_kernel<<<dim3(NCH, NBH), 256>>>(qkv, Sc, kc);
    prefix_kernel<<<dim3(16, NBH), 256>>>(Sc, kc, S0, kc0, out, out_size);
    intra_kernel<<<dim3(NCH, NBH), 256, INTRA_SMEM>>>(qkv, S0, kc0, yh, yl);

    // output projection: out = y @ Wo^T
    hmma_gemm_fp16<<<dim3(8, NTOK / 128), 256, GEMM_SMEM>>>(
        yh, yl, 256, Woh, 256, out, DDIM, 256);
}